// round 1
// baseline (speedup 1.0000x reference)
#include <cuda_runtime.h>
#include <math.h>

// ---------------- problem constants ----------------
#define BB   8
#define CC   256
#define HH   112
#define WW   112
#define HWP  12544              // H*W
#define CHW  3211264            // C*H*W
#define PP   196                // patch_area
#define SS   64                 // split_head_num
#define DD   16384              // C*S
#define A3   3136               // 56*56
#define TGD  56

// ---------------- scratch (static device memory; no runtime allocs) ----------------
__device__ float g_q[BB * CHW];
__device__ float g_k[BB * CHW];
__device__ float g_v[BB * CHW];
__device__ float g_qp[BB * CC * A3];
__device__ float g_kp[BB * CC * A3];
__device__ float g_vp[BB * CC * A3];
__device__ float g_attp_part[16 * BB * PP * PP];   // split-K partials (deterministic)
__device__ float g_attp[BB * PP * PP];
__device__ float g_hpatch[BB * CHW];
__device__ float g_attg[(size_t)BB * A3 * A3];     // 315 MB
__device__ float g_hglob[BB * CC * A3];
__device__ float g_h[BB * CHW];
__device__ float g_spart[BB * 64 * 2];
__device__ float g_stats[BB * 2];

// ---------------- shared 4x4 microkernel for 64x64x16 tiles ----------------
__device__ __forceinline__ void micro16(const float (&As)[16][64],
                                        const float (&Bs)[16][64],
                                        float (&acc)[4][4], int ty, int tx) {
#pragma unroll
    for (int kk = 0; kk < 16; kk++) {
        float a[4], bv[4];
        *(float4*)a  = *(const float4*)&As[kk][ty * 4];
        *(float4*)bv = *(const float4*)&Bs[kk][tx * 4];
#pragma unroll
        for (int i = 0; i < 4; i++)
#pragma unroll
            for (int j = 0; j < 4; j++)
                acc[i][j] += a[i] * bv[j];
    }
}

// ---------------- 1) GroupNorm stats (two-stage, deterministic) ----------------
__global__ void k_gn_stats(const float* __restrict__ x) {
    int b = blockIdx.y;
    const float* xb = x + (size_t)b * CHW;
    float s1 = 0.f, s2 = 0.f;
    for (int i = blockIdx.x * blockDim.x + threadIdx.x; i < CHW;
         i += gridDim.x * blockDim.x) {
        float v = xb[i];
        s1 += v;
        s2 += v * v;
    }
    __shared__ float sm1[256], sm2[256];
    int t = threadIdx.x;
    sm1[t] = s1; sm2[t] = s2;
    __syncthreads();
    for (int o = 128; o > 0; o >>= 1) {
        if (t < o) { sm1[t] += sm1[t + o]; sm2[t] += sm2[t + o]; }
        __syncthreads();
    }
    if (t == 0) {
        g_spart[(b * 64 + blockIdx.x) * 2 + 0] = sm1[0];
        g_spart[(b * 64 + blockIdx.x) * 2 + 1] = sm2[0];
    }
}

__global__ void k_gn_reduce() {
    int b = blockIdx.x, t = threadIdx.x;   // 64 threads
    __shared__ float sm1[64], sm2[64];
    sm1[t] = g_spart[(b * 64 + t) * 2 + 0];
    sm2[t] = g_spart[(b * 64 + t) * 2 + 1];
    __syncthreads();
    for (int o = 32; o > 0; o >>= 1) {
        if (t < o) { sm1[t] += sm1[t + o]; sm2[t] += sm2[t + o]; }
        __syncthreads();
    }
    if (t == 0) {
        g_stats[b * 2 + 0] = sm1[0];
        g_stats[b * 2 + 1] = sm2[0];
    }
}

// ---------------- 2) fused GN + QKV 1x1 conv (GEMM 768x12544x256 per batch) ----------------
__global__ void k_qkv(const float* __restrict__ x,
                      const float* __restrict__ gnw, const float* __restrict__ gnb,
                      const float* __restrict__ wq, const float* __restrict__ bq,
                      const float* __restrict__ wk, const float* __restrict__ bk,
                      const float* __restrict__ wv, const float* __restrict__ bv) {
    int b = blockIdx.z;
    int n0 = blockIdx.x * 64;
    int m0g = blockIdx.y * 64;            // 0..704 over stacked [wq;wk;wv]
    int sel = m0g >> 8;
    int m0 = m0g & 255;
    const float* Wsel = (sel == 0) ? wq : (sel == 1) ? wk : wv;
    const float* Bias = (sel == 0) ? bq : (sel == 1) ? bk : bv;
    float* Out        = (sel == 0) ? g_q : (sel == 1) ? g_k : g_v;

    float mu, rstd;
    {
        float s1 = g_stats[b * 2], s2 = g_stats[b * 2 + 1];
        const float invN = 1.0f / (float)CHW;
        mu = s1 * invN;
        float var = s2 * invN - mu * mu;
        rstd = rsqrtf(var + 1e-5f);
    }

    __shared__ float As[16][64], Bs[16][64];
    int t = threadIdx.x, tx = t & 15, ty = t >> 4;
    float acc[4][4] = {};
    const float* xb = x + (size_t)b * CHW;

    for (int k0 = 0; k0 < 256; k0 += 16) {
        {   // A: weight rows, contiguous along k
            int kk = t & 15, mr = t >> 4;
#pragma unroll
            for (int r = 0; r < 4; r++) {
                int mm = mr + r * 16;
                As[kk][mm] = Wsel[(m0 + mm) * 256 + k0 + kk];
            }
        }
        {   // B: normalized x, contiguous along n
            int nn = t & 63, kr = t >> 6;
#pragma unroll
            for (int r = 0; r < 4; r++) {
                int kk = kr + r * 4;
                int k = k0 + kk;
                float xv = xb[(size_t)k * HWP + n0 + nn];
                Bs[kk][nn] = (xv - mu) * rstd * gnw[k] + gnb[k];
            }
        }
        __syncthreads();
        micro16(As, Bs, acc, ty, tx);
        __syncthreads();
    }
#pragma unroll
    for (int i = 0; i < 4; i++) {
        int m = m0 + ty * 4 + i;
        float bia = Bias[m];
#pragma unroll
        for (int j = 0; j < 4; j++) {
            int n = n0 + tx * 4 + j;
            Out[(size_t)(b * CC + m) * HWP + n] = acc[i][j] + bia;
        }
    }
}

// ---------------- 3) 2x2 average pool of q,k,v ----------------
__global__ void k_pool() {
    int idx = blockIdx.x * blockDim.x + threadIdx.x;
    if (idx >= BB * CC * A3) return;
    int t = idx % A3;
    int bc = idx / A3;
    int ty = t / TGD, tx = t % TGD;
    size_t base = (size_t)bc * HWP + (size_t)(2 * ty) * WW + 2 * tx;
    g_qp[idx] = 0.25f * (g_q[base] + g_q[base + 1] + g_q[base + WW] + g_q[base + WW + 1]);
    g_kp[idx] = 0.25f * (g_k[base] + g_k[base + 1] + g_k[base + WW] + g_k[base + WW + 1]);
    g_vp[idx] = 0.25f * (g_v[base] + g_v[base + 1] + g_v[base + WW] + g_v[base + WW + 1]);
}

// ---------------- 4) patch attention logits (196x196, K=16384, split-K=16) ----------------
__global__ void k_patt() {
    int bz = blockIdx.z;                 // b*16 + ks
    int b = bz >> 4, ks = bz & 15;
    int m0 = blockIdx.y * 64, n0 = blockIdx.x * 64;
    const float* qb = g_q + (size_t)b * CHW;
    const float* kb = g_k + (size_t)b * CHW;
    __shared__ float As[16][64], Bs[16][64];
    int t = threadIdx.x, tx = t & 15, ty = t >> 4;
    float acc[4][4] = {};
    int kbeg = ks * 1024, kend = kbeg + 1024;
    for (int k0 = kbeg; k0 < kend; k0 += 16) {
        int mm = t & 63, kr = t >> 6;
#pragma unroll
        for (int r = 0; r < 4; r++) {
            int kk = kr + r * 4;
            int k = k0 + kk;
            int m = m0 + mm, n = n0 + mm;
            As[kk][mm] = (m < PP) ? qb[(size_t)k * PP + m] : 0.f;
            Bs[kk][mm] = (n < PP) ? kb[(size_t)k * PP + n] : 0.f;
        }
        __syncthreads();
        micro16(As, Bs, acc, ty, tx);
        __syncthreads();
    }
    const float scale = 1.0f / 128.0f;   // (C*S)^-0.5
#pragma unroll
    for (int i = 0; i < 4; i++) {
        int m = m0 + ty * 4 + i;
        if (m >= PP) continue;
#pragma unroll
        for (int j = 0; j < 4; j++) {
            int n = n0 + tx * 4 + j;
            if (n >= PP) continue;
            g_attp_part[((size_t)(ks * BB + b) * PP + m) * PP + n] = acc[i][j] * scale;
        }
    }
}

// ---------------- 5) patch softmax (sums split-K partials, then softmax over row) ----------------
__global__ void k_psm() {
    int row = blockIdx.x;                // b*196 + p
    __shared__ float srow[PP];
    __shared__ float red[256];
    int t = threadIdx.x;
    for (int q = t; q < PP; q += 256) {
        float s = 0.f;
#pragma unroll
        for (int ks = 0; ks < 16; ks++)
            s += g_attp_part[(size_t)ks * (BB * PP * PP) + (size_t)row * PP + q];
        srow[q] = s;
    }
    __syncthreads();
    float mx = -1e30f;
    for (int q = t; q < PP; q += 256) mx = fmaxf(mx, srow[q]);
    red[t] = mx;
    __syncthreads();
    for (int o = 128; o > 0; o >>= 1) { if (t < o) red[t] = fmaxf(red[t], red[t + o]); __syncthreads(); }
    mx = red[0];
    __syncthreads();
    float s = 0.f;
    for (int q = t; q < PP; q += 256) { float e = __expf(srow[q] - mx); srow[q] = e; s += e; }
    red[t] = s;
    __syncthreads();
    for (int o = 128; o > 0; o >>= 1) { if (t < o) red[t] += red[t + o]; __syncthreads(); }
    float inv = 1.0f / red[0];
    for (int q = t; q < PP; q += 256) g_attp[(size_t)row * PP + q] = srow[q] * inv;
}

// ---------------- 6) h_patch = V(16384x196) @ att^T(196x196) ----------------
__global__ void k_hpatch() {
    int b = blockIdx.z;
    int m0 = blockIdx.y * 64;            // d-rows (256 tiles)
    int n0 = blockIdx.x * 64;            // q cols (4 tiles, guard <196)
    const float* vb = g_v + (size_t)b * CHW;
    const float* ab = g_attp + (size_t)b * PP * PP;
    __shared__ float As[16][64], Bs[16][64];
    int t = threadIdx.x, tx = t & 15, ty = t >> 4;
    float acc[4][4] = {};
    for (int k0 = 0; k0 < PP; k0 += 16) {
        int kk = t & 15, mr = t >> 4;
        int k = k0 + kk;
#pragma unroll
        for (int r = 0; r < 4; r++) {
            int mm = mr + r * 16;
            As[kk][mm] = (k < PP) ? vb[(size_t)(m0 + mm) * PP + k] : 0.f;
            int n = n0 + mm;
            Bs[kk][mm] = (k < PP && n < PP) ? ab[(size_t)n * PP + k] : 0.f;
        }
        __syncthreads();
        micro16(As, Bs, acc, ty, tx);
        __syncthreads();
    }
#pragma unroll
    for (int i = 0; i < 4; i++) {
        int m = m0 + ty * 4 + i;
#pragma unroll
        for (int j = 0; j < 4; j++) {
            int n = n0 + tx * 4 + j;
            if (n < PP)
                g_hpatch[(size_t)b * CHW + (size_t)m * PP + n] = acc[i][j];
        }
    }
}

// ---------------- 7) global attention logits (3136x3136, K=256) ----------------
__global__ void k_gatt() {
    int b = blockIdx.z;
    int m0 = blockIdx.y * 64, n0 = blockIdx.x * 64;
    const float* qb = g_qp + (size_t)b * CC * A3;
    const float* kb = g_kp + (size_t)b * CC * A3;
    __shared__ float As[16][64], Bs[16][64];
    int t = threadIdx.x, tx = t & 15, ty = t >> 4;
    float acc[4][4] = {};
    for (int k0 = 0; k0 < 256; k0 += 16) {
        int mm = t & 63, kr = t >> 6;
#pragma unroll
        for (int r = 0; r < 4; r++) {
            int kk = kr + r * 4;
            int k = k0 + kk;
            As[kk][mm] = qb[(size_t)k * A3 + m0 + mm];
            Bs[kk][mm] = kb[(size_t)k * A3 + n0 + mm];
        }
        __syncthreads();
        micro16(As, Bs, acc, ty, tx);
        __syncthreads();
    }
    float* ob = g_attg + (size_t)b * A3 * A3;
#pragma unroll
    for (int i = 0; i < 4; i++)
#pragma unroll
        for (int j = 0; j < 4; j++)
            ob[(size_t)(m0 + ty * 4 + i) * A3 + n0 + tx * 4 + j] = acc[i][j] * 0.0625f;
}

// ---------------- 8) global softmax (row in smem) ----------------
__global__ void k_gsm() {
    float* r = g_attg + (size_t)blockIdx.x * A3;
    __shared__ float srow[A3];
    __shared__ float red[256];
    int t = threadIdx.x;
    float mx = -1e30f;
    for (int i = t; i < A3; i += 256) { float v = r[i]; srow[i] = v; mx = fmaxf(mx, v); }
    red[t] = mx;
    __syncthreads();
    for (int o = 128; o > 0; o >>= 1) { if (t < o) red[t] = fmaxf(red[t], red[t + o]); __syncthreads(); }
    mx = red[0];
    __syncthreads();
    float s = 0.f;
    for (int i = t; i < A3; i += 256) { float e = __expf(srow[i] - mx); srow[i] = e; s += e; }
    red[t] = s;
    __syncthreads();
    for (int o = 128; o > 0; o >>= 1) { if (t < o) red[t] += red[t + o]; __syncthreads(); }
    float inv = 1.0f / red[0];
    for (int i = t; i < A3; i += 256) r[i] = srow[i] * inv;
}

// ---------------- 9) h_glob = Vp(256x3136) @ att^T(3136x3136) ----------------
__global__ void k_hglob() {
    int b = blockIdx.z;
    int m0 = blockIdx.y * 64;            // channel tile (4)
    int n0 = blockIdx.x * 64;            // position tile (49)
    const float* vb = g_vp + (size_t)b * CC * A3;
    const float* ab = g_attg + (size_t)b * A3 * A3;
    __shared__ float As[16][64], Bs[16][64];
    int t = threadIdx.x, tx = t & 15, ty = t >> 4;
    float acc[4][4] = {};
    for (int k0 = 0; k0 < A3; k0 += 16) {
        int kk = t & 15, mr = t >> 4;
#pragma unroll
        for (int r = 0; r < 4; r++) {
            int mm = mr + r * 16;
            As[kk][mm] = vb[(size_t)(m0 + mm) * A3 + k0 + kk];
            Bs[kk][mm] = ab[(size_t)(n0 + mm) * A3 + k0 + kk];
        }
        __syncthreads();
        micro16(As, Bs, acc, ty, tx);
        __syncthreads();
    }
    float* ob = g_hglob + (size_t)b * CC * A3;
#pragma unroll
    for (int i = 0; i < 4; i++)
#pragma unroll
        for (int j = 0; j < 4; j++)
            ob[(size_t)(m0 + ty * 4 + i) * A3 + n0 + tx * 4 + j] = acc[i][j];
}

// ---------------- 10) combine: h = 0.75*h_patch + 0.25*bilinear_up2x(h_glob) ----------------
__global__ void k_comb() {
    int idx = blockIdx.x * blockDim.x + threadIdx.x;
    if (idx >= BB * CHW) return;
    int hw = idx % HWP;
    int bc = idx / HWP;
    int i = hw / WW, j = hw % WW;
    float sy = 0.5f * i - 0.25f;
    int y0 = (int)floorf(sy);
    float fy = sy - (float)y0;
    int y0c = max(y0, 0), y1c = min(y0 + 1, TGD - 1);
    float sx = 0.5f * j - 0.25f;
    int x0 = (int)floorf(sx);
    float fx = sx - (float)x0;
    int x0c = max(x0, 0), x1c = min(x0 + 1, TGD - 1);
    const float* hg = g_hglob + (size_t)bc * A3;
    float v00 = hg[y0c * TGD + x0c], v01 = hg[y0c * TGD + x1c];
    float v10 = hg[y1c * TGD + x0c], v11 = hg[y1c * TGD + x1c];
    float bil = (1.f - fy) * ((1.f - fx) * v00 + fx * v01) +
                fy * ((1.f - fx) * v10 + fx * v11);
    g_h[idx] = 0.75f * g_hpatch[idx] + 0.25f * bil;
}

// ---------------- 11) proj 1x1 conv + residual ----------------
__global__ void k_proj(const float* __restrict__ x, const float* __restrict__ wp,
                       float* __restrict__ out) {
    int b = blockIdx.z;
    int m0 = blockIdx.y * 64;            // out channel (4)
    int n0 = blockIdx.x * 64;            // spatial (196)
    const float* hb = g_h + (size_t)b * CHW;
    __shared__ float As[16][64], Bs[16][64];
    int t = threadIdx.x, tx = t & 15, ty = t >> 4;
    float acc[4][4] = {};
    for (int k0 = 0; k0 < 256; k0 += 16) {
        {
            int kk = t & 15, mr = t >> 4;
#pragma unroll
            for (int r = 0; r < 4; r++) {
                int mm = mr + r * 16;
                As[kk][mm] = wp[(m0 + mm) * 256 + k0 + kk];
            }
        }
        {
            int nn = t & 63, kr = t >> 6;
#pragma unroll
            for (int r = 0; r < 4; r++) {
                int kk = kr + r * 4;
                Bs[kk][nn] = hb[(size_t)(k0 + kk) * HWP + n0 + nn];
            }
        }
        __syncthreads();
        micro16(As, Bs, acc, ty, tx);
        __syncthreads();
    }
#pragma unroll
    for (int i = 0; i < 4; i++) {
        int m = m0 + ty * 4 + i;
#pragma unroll
        for (int j = 0; j < 4; j++) {
            int n = n0 + tx * 4 + j;
            size_t o = (size_t)b * CHW + (size_t)m * HWP + n;
            out[o] = x[o] + acc[i][j];
        }
    }
}

// ---------------- launch ----------------
extern "C" void kernel_launch(void* const* d_in, const int* in_sizes, int n_in,
                              void* d_out, int out_size) {
    const float* x   = (const float*)d_in[0];
    const float* gnw = (const float*)d_in[1];
    const float* gnb = (const float*)d_in[2];
    const float* wq  = (const float*)d_in[3];
    const float* bq  = (const float*)d_in[4];
    const float* wk  = (const float*)d_in[5];
    const float* bk  = (const float*)d_in[6];
    const float* wv  = (const float*)d_in[7];
    const float* bv  = (const float*)d_in[8];
    const float* wp  = (const float*)d_in[9];
    float* out = (float*)d_out;

    k_gn_stats<<<dim3(64, 8), 256>>>(x);
    k_gn_reduce<<<8, 64>>>();
    k_qkv<<<dim3(196, 12, 8), 256>>>(x, gnw, gnb, wq, bq, wk, bk, wv, bv);
    k_pool<<<(BB * CC * A3 + 255) / 256, 256>>>();
    k_patt<<<dim3(4, 4, 128), 256>>>();
    k_psm<<<BB * PP, 256>>>();
    k_hpatch<<<dim3(4, 256, 8), 256>>>();
    k_gatt<<<dim3(49, 49, 8), 256>>>();
    k_gsm<<<BB * A3, 256>>>();
    k_hglob<<<dim3(49, 4, 8), 256>>>();
    k_comb<<<(BB * CHW + 255) / 256, 256>>>();
    k_proj<<<dim3(196, 4, 8), 256>>>(x, wp, out);
}

// round 3
// speedup vs baseline: 1.9850x; 1.9850x over previous
#include <cuda_runtime.h>
#include <math.h>

// ---------------- problem constants ----------------
#define BB   8
#define CC   256
#define HH   112
#define WW   112
#define HWP  12544              // H*W
#define CHW  3211264            // C*H*W
#define PP   196                // patch_area
#define A3   3136               // 56*56
#define TGD  56
#define TS   72                 // smem tile stride (bank-conflict-free fragment loads)

// ---------------- scratch (static device memory; no runtime allocs) ----------------
__device__ float g_q[BB * CHW];
__device__ float g_k[BB * CHW];
__device__ float g_v[BB * CHW];
__device__ float g_qp[BB * CC * A3];
__device__ float g_kp[BB * CC * A3];
__device__ float g_vp[BB * CC * A3];
__device__ float g_attp_part[16 * BB * PP * PP];   // split-K partials (deterministic)
__device__ float g_attp[BB * PP * PP];
__device__ float g_hpatch[BB * CHW];
__device__ float g_attg[(size_t)BB * A3 * A3];     // 315 MB
__device__ float g_hglob[BB * CC * A3];
__device__ float g_h[BB * CHW];
__device__ float g_spart[BB * 64 * 2];
__device__ float g_stats[BB * 2];

// ---------------- tf32 helpers ----------------
__device__ __forceinline__ unsigned f2tf(float f) {
    unsigned u;
    asm("cvt.rna.tf32.f32 %0, %1;" : "=r"(u) : "f"(f));
    return u;
}

__device__ __forceinline__ void mma_tf32(float* c, const unsigned* a, const unsigned* b) {
    asm volatile(
        "mma.sync.aligned.m16n8k8.row.col.f32.tf32.tf32.f32 "
        "{%0,%1,%2,%3}, {%4,%5,%6,%7}, {%8,%9}, {%0,%1,%2,%3};"
        : "+f"(c[0]), "+f"(c[1]), "+f"(c[2]), "+f"(c[3])
        : "r"(a[0]), "r"(a[1]), "r"(a[2]), "r"(a[3]), "r"(b[0]), "r"(b[1]));
}

// Warp computes a 16x64 slab of the 64x64 block tile (warp w -> rows w*16..w*16+15).
__device__ __forceinline__ void wmicro(const unsigned (*As)[TS], const unsigned (*Bs)[TS],
                                       float (&acc)[8][4], int warp, int lane) {
    int m0 = warp * 16;
    int gr = lane >> 2, tg = lane & 3;
#pragma unroll
    for (int kt = 0; kt < 2; kt++) {
        int k0 = kt * 8;
        unsigned a[4];
        a[0] = As[k0 + tg][m0 + gr];
        a[1] = As[k0 + tg][m0 + gr + 8];
        a[2] = As[k0 + tg + 4][m0 + gr];
        a[3] = As[k0 + tg + 4][m0 + gr + 8];
#pragma unroll
        for (int nt = 0; nt < 8; nt++) {
            unsigned b[2];
            b[0] = Bs[k0 + tg][nt * 8 + gr];
            b[1] = Bs[k0 + tg + 4][nt * 8 + gr];
            mma_tf32(acc[nt], a, b);
        }
    }
}

// ---------------- 1) GroupNorm stats (two-stage, deterministic) ----------------
__global__ void k_gn_stats(const float* __restrict__ x) {
    int b = blockIdx.y;
    const float* xb = x + (size_t)b * CHW;
    float s1 = 0.f, s2 = 0.f;
    for (int i = blockIdx.x * blockDim.x + threadIdx.x; i < CHW;
         i += gridDim.x * blockDim.x) {
        float v = xb[i];
        s1 += v;
        s2 += v * v;
    }
    __shared__ float sm1[256], sm2[256];
    int t = threadIdx.x;
    sm1[t] = s1; sm2[t] = s2;
    __syncthreads();
    for (int o = 128; o > 0; o >>= 1) {
        if (t < o) { sm1[t] += sm1[t + o]; sm2[t] += sm2[t + o]; }
        __syncthreads();
    }
    if (t == 0) {
        g_spart[(b * 64 + blockIdx.x) * 2 + 0] = sm1[0];
        g_spart[(b * 64 + blockIdx.x) * 2 + 1] = sm2[0];
    }
}

__global__ void k_gn_reduce() {
    int b = blockIdx.x, t = threadIdx.x;   // 64 threads
    __shared__ float sm1[64], sm2[64];
    sm1[t] = g_spart[(b * 64 + t) * 2 + 0];
    sm2[t] = g_spart[(b * 64 + t) * 2 + 1];
    __syncthreads();
    for (int o = 32; o > 0; o >>= 1) {
        if (t < o) { sm1[t] += sm1[t + o]; sm2[t] += sm2[t + o]; }
        __syncthreads();
    }
    if (t == 0) {
        g_stats[b * 2 + 0] = sm1[0];
        g_stats[b * 2 + 1] = sm2[0];
    }
}

// ---------------- 2) fused GN + QKV 1x1 conv ----------------
__global__ void k_qkv(const float* __restrict__ x,
                      const float* __restrict__ gnw, const float* __restrict__ gnb,
                      const float* __restrict__ wq, const float* __restrict__ bq,
                      const float* __restrict__ wk, const float* __restrict__ bk,
                      const float* __restrict__ wv, const float* __restrict__ bv) {
    int b = blockIdx.z;
    int n0 = blockIdx.x * 64;
    int m0g = blockIdx.y * 64;            // 0..704 over stacked [wq;wk;wv]
    int sel = m0g >> 8;
    int m0 = m0g & 255;
    const float* Wsel = (sel == 0) ? wq : (sel == 1) ? wk : wv;
    const float* Bias = (sel == 0) ? bq : (sel == 1) ? bk : bv;
    float* Out        = (sel == 0) ? g_q : (sel == 1) ? g_k : g_v;

    float mu, rstd;
    {
        float s1 = g_stats[b * 2], s2 = g_stats[b * 2 + 1];
        const float invN = 1.0f / (float)CHW;
        mu = s1 * invN;
        float var = s2 * invN - mu * mu;
        rstd = rsqrtf(var + 1e-5f);
    }

    __shared__ unsigned As[16][TS], Bs[16][TS];
    int t = threadIdx.x, warp = t >> 5, lane = t & 31;
    float acc[8][4] = {};
    const float* xb = x + (size_t)b * CHW;

    for (int k0 = 0; k0 < 256; k0 += 16) {
        {   // A: weight rows, k contiguous in gmem
            int kk = t & 15, mr = t >> 4;
#pragma unroll
            for (int r = 0; r < 8; r++) {
                int mm = mr + r * 8;
                As[kk][mm] = f2tf(Wsel[(m0 + mm) * 256 + k0 + kk]);
            }
        }
        {   // B: normalized x, n contiguous in gmem
            int nn = t & 63, kr = t >> 6;
#pragma unroll
            for (int r = 0; r < 8; r++) {
                int kk = kr + r * 2;
                int k = k0 + kk;
                float xv = xb[(size_t)k * HWP + n0 + nn];
                Bs[kk][nn] = f2tf((xv - mu) * rstd * gnw[k] + gnb[k]);
            }
        }
        __syncthreads();
        wmicro(As, Bs, acc, warp, lane);
        __syncthreads();
    }
    int gr = lane >> 2, tg = lane & 3;
    int m = m0 + warp * 16 + gr;
    float b0v = Bias[m], b1v = Bias[m + 8];
#pragma unroll
    for (int nt = 0; nt < 8; nt++) {
        int n = n0 + nt * 8 + tg * 2;
        float2 v0 = make_float2(acc[nt][0] + b0v, acc[nt][1] + b0v);
        float2 v1 = make_float2(acc[nt][2] + b1v, acc[nt][3] + b1v);
        *(float2*)&Out[(size_t)(b * CC + m) * HWP + n]       = v0;
        *(float2*)&Out[(size_t)(b * CC + m + 8) * HWP + n]   = v1;
    }
}

// ---------------- 3) 2x2 average pool of q,k,v ----------------
__global__ void k_pool() {
    int idx = blockIdx.x * blockDim.x + threadIdx.x;
    if (idx >= BB * CC * A3) return;
    int t = idx % A3;
    int bc = idx / A3;
    int ty = t / TGD, tx = t % TGD;
    size_t base = (size_t)bc * HWP + (size_t)(2 * ty) * WW + 2 * tx;
    g_qp[idx] = 0.25f * (g_q[base] + g_q[base + 1] + g_q[base + WW] + g_q[base + WW + 1]);
    g_kp[idx] = 0.25f * (g_k[base] + g_k[base + 1] + g_k[base + WW] + g_k[base + WW + 1]);
    g_vp[idx] = 0.25f * (g_v[base] + g_v[base + 1] + g_v[base + WW] + g_v[base + WW + 1]);
}

// ---------------- 4) patch attention logits (196x196, K=16384, split-K=16) ----------------
__global__ void k_patt() {
    int bz = blockIdx.z;                 // b*16 + ks
    int b = bz >> 4, ks = bz & 15;
    int m0 = blockIdx.y * 64, n0 = blockIdx.x * 64;
    const float* qb = g_q + (size_t)b * CHW;
    const float* kb = g_k + (size_t)b * CHW;
    __shared__ unsigned As[16][TS], Bs[16][TS];
    int t = threadIdx.x, warp = t >> 5, lane = t & 31;
    float acc[8][4] = {};
    int kbeg = ks * 1024, kend = kbeg + 1024;
    for (int k0 = kbeg; k0 < kend; k0 += 16) {
        int nn = t & 63, kr = t >> 6;
#pragma unroll
        for (int r = 0; r < 8; r++) {
            int kk = kr + r * 2;
            int k = k0 + kk;
            int m = m0 + nn, n = n0 + nn;
            As[kk][nn] = (m < PP) ? f2tf(qb[(size_t)k * PP + m]) : 0u;
            Bs[kk][nn] = (n < PP) ? f2tf(kb[(size_t)k * PP + n]) : 0u;
        }
        __syncthreads();
        wmicro(As, Bs, acc, warp, lane);
        __syncthreads();
    }
    const float scale = 1.0f / 128.0f;   // (C*S)^-0.5
    int gr = lane >> 2, tg = lane & 3;
    float* ob = g_attp_part + (size_t)(ks * BB + b) * PP * PP;
#pragma unroll
    for (int nt = 0; nt < 8; nt++) {
        int n = n0 + nt * 8 + tg * 2;
#pragma unroll
        for (int half = 0; half < 2; half++) {
            int m = m0 + warp * 16 + gr + half * 8;
            if (m >= PP) continue;
            if (n < PP)     ob[(size_t)m * PP + n]     = acc[nt][half * 2 + 0] * scale;
            if (n + 1 < PP) ob[(size_t)m * PP + n + 1] = acc[nt][half * 2 + 1] * scale;
        }
    }
}

// ---------------- 5) patch softmax (sums split-K partials, then softmax over row) ----------------
__global__ void k_psm() {
    int row = blockIdx.x;                // b*196 + p
    __shared__ float srow[PP];
    __shared__ float red[256];
    int t = threadIdx.x;
    for (int q = t; q < PP; q += 256) {
        float s = 0.f;
#pragma unroll
        for (int ks = 0; ks < 16; ks++)
            s += g_attp_part[(size_t)ks * (BB * PP * PP) + (size_t)row * PP + q];
        srow[q] = s;
    }
    __syncthreads();
    float mx = -1e30f;
    for (int q = t; q < PP; q += 256) mx = fmaxf(mx, srow[q]);
    red[t] = mx;
    __syncthreads();
    for (int o = 128; o > 0; o >>= 1) { if (t < o) red[t] = fmaxf(red[t], red[t + o]); __syncthreads(); }
    mx = red[0];
    __syncthreads();
    float s = 0.f;
    for (int q = t; q < PP; q += 256) { float e = __expf(srow[q] - mx); srow[q] = e; s += e; }
    red[t] = s;
    __syncthreads();
    for (int o = 128; o > 0; o >>= 1) { if (t < o) red[t] += red[t + o]; __syncthreads(); }
    float inv = 1.0f / red[0];
    for (int q = t; q < PP; q += 256) g_attp[(size_t)row * PP + q] = srow[q] * inv;
}

// ---------------- 6) h_patch = V(16384x196) @ att^T(196x196) ----------------
__global__ void k_hpatch() {
    int b = blockIdx.z;
    int m0 = blockIdx.y * 64;            // d-rows (256 tiles)
    int n0 = blockIdx.x * 64;            // q cols (4 tiles, guard <196)
    const float* vb = g_v + (size_t)b * CHW;
    const float* ab = g_attp + (size_t)b * PP * PP;
    __shared__ unsigned As[16][TS], Bs[16][TS];
    int t = threadIdx.x, warp = t >> 5, lane = t & 31;
    float acc[8][4] = {};
    for (int k0 = 0; k0 < PP; k0 += 16) {
        int kk = t & 15, mr = t >> 4;
        int k = k0 + kk;
#pragma unroll
        for (int r = 0; r < 8; r++) {
            int mm = mr + r * 8;
            As[kk][mm] = (k < PP) ? f2tf(vb[(size_t)(m0 + mm) * PP + k]) : 0u;
            int n = n0 + mm;
            Bs[kk][mm] = (k < PP && n < PP) ? f2tf(ab[(size_t)n * PP + k]) : 0u;
        }
        __syncthreads();
        wmicro(As, Bs, acc, warp, lane);
        __syncthreads();
    }
    int gr = lane >> 2, tg = lane & 3;
    float* ob = g_hpatch + (size_t)b * CHW;
#pragma unroll
    for (int nt = 0; nt < 8; nt++) {
        int n = n0 + nt * 8 + tg * 2;
#pragma unroll
        for (int half = 0; half < 2; half++) {
            int m = m0 + warp * 16 + gr + half * 8;
            if (n < PP)     ob[(size_t)m * PP + n]     = acc[nt][half * 2 + 0];
            if (n + 1 < PP) ob[(size_t)m * PP + n + 1] = acc[nt][half * 2 + 1];
        }
    }
}

// ---------------- 7) global attention logits (3136x3136, K=256) ----------------
__global__ void k_gatt() {
    int b = blockIdx.z;
    int m0 = blockIdx.y * 64, n0 = blockIdx.x * 64;
    const float* qb = g_qp + (size_t)b * CC * A3;
    const float* kb = g_kp + (size_t)b * CC * A3;
    __shared__ unsigned As[16][TS], Bs[16][TS];
    int t = threadIdx.x, warp = t >> 5, lane = t & 31;
    float acc[8][4] = {};
    for (int k0 = 0; k0 < 256; k0 += 16) {
        int nn = t & 63, kr = t >> 6;
#pragma unroll
        for (int r = 0; r < 8; r++) {
            int kk = kr + r * 2;
            int k = k0 + kk;
            As[kk][nn] = f2tf(qb[(size_t)k * A3 + m0 + nn]);
            Bs[kk][nn] = f2tf(kb[(size_t)k * A3 + n0 + nn]);
        }
        __syncthreads();
        wmicro(As, Bs, acc, warp, lane);
        __syncthreads();
    }
    float* ob = g_attg + (size_t)b * A3 * A3;
    int gr = lane >> 2, tg = lane & 3;
    int m = m0 + warp * 16 + gr;
#pragma unroll
    for (int nt = 0; nt < 8; nt++) {
        int n = n0 + nt * 8 + tg * 2;
        float2 v0 = make_float2(acc[nt][0] * 0.0625f, acc[nt][1] * 0.0625f);
        float2 v1 = make_float2(acc[nt][2] * 0.0625f, acc[nt][3] * 0.0625f);
        *(float2*)&ob[(size_t)m * A3 + n]       = v0;
        *(float2*)&ob[(size_t)(m + 8) * A3 + n] = v1;
    }
}

// ---------------- 8) global softmax (row in smem) ----------------
__global__ void k_gsm() {
    float* r = g_attg + (size_t)blockIdx.x * A3;
    __shared__ float srow[A3];
    __shared__ float red[256];
    int t = threadIdx.x;
    float mx = -1e30f;
    for (int i = t; i < A3; i += 256) { float v = r[i]; srow[i] = v; mx = fmaxf(mx, v); }
    red[t] = mx;
    __syncthreads();
    for (int o = 128; o > 0; o >>= 1) { if (t < o) red[t] = fmaxf(red[t], red[t + o]); __syncthreads(); }
    mx = red[0];
    __syncthreads();
    float s = 0.f;
    for (int i = t; i < A3; i += 256) { float e = __expf(srow[i] - mx); srow[i] = e; s += e; }
    red[t] = s;
    __syncthreads();
    for (int o = 128; o > 0; o >>= 1) { if (t < o) red[t] += red[t + o]; __syncthreads(); }
    float inv = 1.0f / red[0];
    for (int i = t; i < A3; i += 256) r[i] = srow[i] * inv;
}

// ---------------- 9) h_glob = Vp(256x3136) @ att^T(3136x3136) ----------------
__global__ void k_hglob() {
    int b = blockIdx.z;
    int m0 = blockIdx.y * 64;            // channel tile (4)
    int n0 = blockIdx.x * 64;            // position tile (49)
    const float* vb = g_vp + (size_t)b * CC * A3;
    const float* ab = g_attg + (size_t)b * A3 * A3;
    __shared__ unsigned As[16][TS], Bs[16][TS];
    int t = threadIdx.x, warp = t >> 5, lane = t & 31;
    float acc[8][4] = {};
    for (int k0 = 0; k0 < A3; k0 += 16) {
        int kk = t & 15, mr = t >> 4;
#pragma unroll
        for (int r = 0; r < 8; r++) {
            int mm = mr + r * 8;
            As[kk][mm] = f2tf(vb[(size_t)(m0 + mm) * A3 + k0 + kk]);
            Bs[kk][mm] = f2tf(ab[(size_t)(n0 + mm) * A3 + k0 + kk]);
        }
        __syncthreads();
        wmicro(As, Bs, acc, warp, lane);
        __syncthreads();
    }
    float* ob = g_hglob + (size_t)b * CC * A3;
    int gr = lane >> 2, tg = lane & 3;
    int m = m0 + warp * 16 + gr;
#pragma unroll
    for (int nt = 0; nt < 8; nt++) {
        int n = n0 + nt * 8 + tg * 2;
        *(float2*)&ob[(size_t)m * A3 + n]       = make_float2(acc[nt][0], acc[nt][1]);
        *(float2*)&ob[(size_t)(m + 8) * A3 + n] = make_float2(acc[nt][2], acc[nt][3]);
    }
}

// ---------------- 10) combine: h = 0.75*h_patch + 0.25*bilinear_up2x(h_glob) ----------------
__global__ void k_comb() {
    int idx = blockIdx.x * blockDim.x + threadIdx.x;
    if (idx >= BB * CHW) return;
    int hw = idx % HWP;
    int bc = idx / HWP;
    int i = hw / WW, j = hw % WW;
    float sy = 0.5f * i - 0.25f;
    int y0 = (int)floorf(sy);
    float fy = sy - (float)y0;
    int y0c = max(y0, 0), y1c = min(y0 + 1, TGD - 1);
    float sx = 0.5f * j - 0.25f;
    int x0 = (int)floorf(sx);
    float fx = sx - (float)x0;
    int x0c = max(x0, 0), x1c = min(x0 + 1, TGD - 1);
    const float* hg = g_hglob + (size_t)bc * A3;
    float v00 = hg[y0c * TGD + x0c], v01 = hg[y0c * TGD + x1c];
    float v10 = hg[y1c * TGD + x0c], v11 = hg[y1c * TGD + x1c];
    float bil = (1.f - fy) * ((1.f - fx) * v00 + fx * v01) +
                fy * ((1.f - fx) * v10 + fx * v11);
    g_h[idx] = 0.75f * g_hpatch[idx] + 0.25f * bil;
}

// ---------------- 11) proj 1x1 conv + residual ----------------
__global__ void k_proj(const float* __restrict__ x, const float* __restrict__ wp,
                       float* __restrict__ out) {
    int b = blockIdx.z;
    int m0 = blockIdx.y * 64;            // out channel (4)
    int n0 = blockIdx.x * 64;            // spatial (196)
    const float* hb = g_h + (size_t)b * CHW;
    __shared__ unsigned As[16][TS], Bs[16][TS];
    int t = threadIdx.x, warp = t >> 5, lane = t & 31;
    float acc[8][4] = {};
    for (int k0 = 0; k0 < 256; k0 += 16) {
        {
            int kk = t & 15, mr = t >> 4;
#pragma unroll
            for (int r = 0; r < 8; r++) {
                int mm = mr + r * 8;
                As[kk][mm] = f2tf(wp[(m0 + mm) * 256 + k0 + kk]);
            }
        }
        {
            int nn = t & 63, kr = t >> 6;
#pragma unroll
            for (int r = 0; r < 8; r++) {
                int kk = kr + r * 2;
                Bs[kk][nn] = f2tf(hb[(size_t)(k0 + kk) * HWP + n0 + nn]);
            }
        }
        __syncthreads();
        wmicro(As, Bs, acc, warp, lane);
        __syncthreads();
    }
    int gr = lane >> 2, tg = lane & 3;
    int m = m0 + warp * 16 + gr;
#pragma unroll
    for (int nt = 0; nt < 8; nt++) {
        int n = n0 + nt * 8 + tg * 2;
        size_t o0 = (size_t)b * CHW + (size_t)m * HWP + n;
        size_t o1 = (size_t)b * CHW + (size_t)(m + 8) * HWP + n;
        float2 x0 = *(const float2*)&x[o0];
        float2 x1 = *(const float2*)&x[o1];
        *(float2*)&out[o0] = make_float2(x0.x + acc[nt][0], x0.y + acc[nt][1]);
        *(float2*)&out[o1] = make_float2(x1.x + acc[nt][2], x1.y + acc[nt][3]);
    }
}

// ---------------- launch ----------------
extern "C" void kernel_launch(void* const* d_in, const int* in_sizes, int n_in,
                              void* d_out, int out_size) {
    const float* x   = (const float*)d_in[0];
    const float* gnw = (const float*)d_in[1];
    const float* gnb = (const float*)d_in[2];
    const float* wq  = (const float*)d_in[3];
    const float* bq  = (const float*)d_in[4];
    const float* wk  = (const float*)d_in[5];
    const float* bk  = (const float*)d_in[6];
    const float* wv  = (const float*)d_in[7];
    const float* bv  = (const float*)d_in[8];
    const float* wp  = (const float*)d_in[9];
    float* out = (float*)d_out;

    k_gn_stats<<<dim3(64, 8), 256>>>(x);
    k_gn_reduce<<<8, 64>>>();
    k_qkv<<<dim3(196, 12, 8), 128>>>(x, gnw, gnb, wq, bq, wk, bk, wv, bv);
    k_pool<<<(BB * CC * A3 + 255) / 256, 256>>>();
    k_patt<<<dim3(4, 4, 128), 128>>>();
    k_psm<<<BB * PP, 256>>>();
    k_hpatch<<<dim3(4, 256, 8), 128>>>();
    k_gatt<<<dim3(49, 49, 8), 128>>>();
    k_gsm<<<BB * A3, 256>>>();
    k_hglob<<<dim3(49, 4, 8), 128>>>();
    k_comb<<<(BB * CHW + 255) / 256, 256>>>();
    k_proj<<<dim3(196, 4, 8), 128>>>(x, wp, out);
}

// round 5
// speedup vs baseline: 3.6028x; 1.8151x over previous
#include <cuda_runtime.h>
#include <math.h>

// ---------------- problem constants ----------------
#define BB   8
#define CC   256
#define HH   112
#define WW   112
#define HWP  12544              // H*W
#define CHW  3211264            // C*H*W
#define PP   196                // patch_area
#define A3   3136               // 56*56
#define TGD  56

#define KST  132                // k-major smem stride ([16][132])
#define MST  20                 // m/n-major smem stride ([128][20])

// ---------------- scratch (static device memory; no runtime allocs) ----------------
__device__ float g_xn[BB * CHW];
__device__ float g_q[BB * CHW];
__device__ float g_k[BB * CHW];
__device__ float g_v[BB * CHW];
__device__ float g_qp[BB * CC * A3];
__device__ float g_kp[BB * CC * A3];
__device__ float g_vp[BB * CC * A3];
__device__ float g_attp_part[16 * BB * PP * PP];
__device__ float g_attp[BB * PP * PP];
__device__ float g_hpatch[BB * CHW];
__device__ float g_attg[(size_t)BB * A3 * A3];
__device__ float g_hglob[BB * CC * A3];
__device__ float g_h[BB * CHW];
__device__ float g_spart[BB * 64 * 2];
__device__ float g_stats[BB * 2];

// ---------------- primitives ----------------
__device__ __forceinline__ void mma_tf32(float* c, const unsigned* a, const unsigned* b) {
    asm volatile(
        "mma.sync.aligned.m16n8k8.row.col.f32.tf32.tf32.f32 "
        "{%0,%1,%2,%3}, {%4,%5,%6,%7}, {%8,%9}, {%0,%1,%2,%3};"
        : "+f"(c[0]), "+f"(c[1]), "+f"(c[2]), "+f"(c[3])
        : "r"(a[0]), "r"(a[1]), "r"(a[2]), "r"(a[3]), "r"(b[0]), "r"(b[1]));
}

__device__ __forceinline__ void cp16(unsigned dst, const void* src, bool v) {
    asm volatile("cp.async.cg.shared.global [%0], [%1], 16, %2;"
                 :: "r"(dst), "l"(src), "r"(v ? 16 : 0));
}
__device__ __forceinline__ void cp_commit() { asm volatile("cp.async.commit_group;"); }
template <int N>
__device__ __forceinline__ void cp_wait() { asm volatile("cp.async.wait_group %0;" :: "n"(N)); }

__device__ __forceinline__ unsigned sptr(const void* p) {
    return (unsigned)__cvta_generic_to_shared(p);
}
__device__ __forceinline__ unsigned fu(float f) { return __float_as_uint(f); }

// 128x128 block, 256 threads, 8 warps: warp w -> m-slab 32*(w>>1), n-slab 64*(w&1).
// AK: A smem is k-major [16][KST] (index k*KST+m); else m-major [128][MST] (m*MST+k).
// BK: B smem is k-major [16][KST] (k*KST+n);     else n-major [128][MST] (n*MST+k).
template <bool AK, bool BK>
__device__ __forceinline__ void tile_mma(const float* As, const float* Bs,
                                         float (&acc)[2][8][4], int warp, int lane) {
    const int m0w = 32 * (warp >> 1), n0w = 64 * (warp & 1);
    const int gr = lane >> 2, tg = lane & 3;
#pragma unroll
    for (int kt = 0; kt < 2; kt++) {
        const int k0 = kt * 8;
        unsigned a[2][4];
#pragma unroll
        for (int mt = 0; mt < 2; mt++) {
            const int mb = m0w + mt * 16;
            if (AK) {
                a[mt][0] = fu(As[(k0 + tg) * KST + mb + gr]);
                a[mt][1] = fu(As[(k0 + tg) * KST + mb + gr + 8]);
                a[mt][2] = fu(As[(k0 + tg + 4) * KST + mb + gr]);
                a[mt][3] = fu(As[(k0 + tg + 4) * KST + mb + gr + 8]);
            } else {
                a[mt][0] = fu(As[(mb + gr) * MST + k0 + tg]);
                a[mt][1] = fu(As[(mb + gr + 8) * MST + k0 + tg]);
                a[mt][2] = fu(As[(mb + gr) * MST + k0 + tg + 4]);
                a[mt][3] = fu(As[(mb + gr + 8) * MST + k0 + tg + 4]);
            }
        }
#pragma unroll
        for (int nt = 0; nt < 8; nt++) {
            unsigned b[2];
            const int nb = n0w + nt * 8 + gr;
            if (BK) {
                b[0] = fu(Bs[(k0 + tg) * KST + nb]);
                b[1] = fu(Bs[(k0 + tg + 4) * KST + nb]);
            } else {
                b[0] = fu(Bs[nb * MST + k0 + tg]);
                b[1] = fu(Bs[nb * MST + k0 + tg + 4]);
            }
            mma_tf32(acc[0][nt], a[0], b);
            mma_tf32(acc[1][nt], a[1], b);
        }
    }
}

// ---------------- 1) GroupNorm stats ----------------
__global__ void k_gn_stats(const float* __restrict__ x) {
    int b = blockIdx.y;
    const float* xb = x + (size_t)b * CHW;
    float s1 = 0.f, s2 = 0.f;
    for (int i = blockIdx.x * blockDim.x + threadIdx.x; i < CHW;
         i += gridDim.x * blockDim.x) {
        float v = xb[i];
        s1 += v; s2 += v * v;
    }
    __shared__ float sm1[256], sm2[256];
    int t = threadIdx.x;
    sm1[t] = s1; sm2[t] = s2;
    __syncthreads();
    for (int o = 128; o > 0; o >>= 1) {
        if (t < o) { sm1[t] += sm1[t + o]; sm2[t] += sm2[t + o]; }
        __syncthreads();
    }
    if (t == 0) {
        g_spart[(b * 64 + blockIdx.x) * 2 + 0] = sm1[0];
        g_spart[(b * 64 + blockIdx.x) * 2 + 1] = sm2[0];
    }
}

__global__ void k_gn_reduce() {
    int b = blockIdx.x, t = threadIdx.x;
    __shared__ float sm1[64], sm2[64];
    sm1[t] = g_spart[(b * 64 + t) * 2 + 0];
    sm2[t] = g_spart[(b * 64 + t) * 2 + 1];
    __syncthreads();
    for (int o = 32; o > 0; o >>= 1) {
        if (t < o) { sm1[t] += sm1[t + o]; sm2[t] += sm2[t + o]; }
        __syncthreads();
    }
    if (t == 0) {
        g_stats[b * 2 + 0] = sm1[0];
        g_stats[b * 2 + 1] = sm2[0];
    }
}

// ---------------- 1b) apply GN elementwise -> g_xn ----------------
__global__ void k_xn(const float* __restrict__ x,
                     const float* __restrict__ gnw, const float* __restrict__ gnb) {
    int idx = blockIdx.x * blockDim.x + threadIdx.x;   // float4 index
    if (idx >= BB * CHW / 4) return;
    int fi = idx * 4;
    int b = fi / CHW;
    int rem = fi - b * CHW;
    int c = rem / HWP;
    float s1 = g_stats[b * 2], s2 = g_stats[b * 2 + 1];
    const float invN = 1.0f / (float)CHW;
    float mu = s1 * invN;
    float rstd = rsqrtf(s2 * invN - mu * mu + 1e-5f);
    float sc = rstd * gnw[c];
    float sh = gnb[c] - mu * sc;
    float4 v = *(const float4*)&x[fi];
    *(float4*)&g_xn[fi] = make_float4(v.x * sc + sh, v.y * sc + sh,
                                      v.z * sc + sh, v.w * sc + sh);
}

// ---------------- 2) QKV 1x1 conv: A=W (m-major), B=xn (k-major) ----------------
__global__ void k_qkv(const float* __restrict__ wq, const float* __restrict__ bq,
                      const float* __restrict__ wk, const float* __restrict__ bk,
                      const float* __restrict__ wv, const float* __restrict__ bv) {
    const int b = blockIdx.z;
    const int n0 = blockIdx.x * 128;
    const int m0g = blockIdx.y * 128;
    const int sel = m0g >> 8;
    const int m0 = m0g & 255;
    const float* Wsel = (sel == 0) ? wq : (sel == 1) ? wk : wv;
    const float* Bias = (sel == 0) ? bq : (sel == 1) ? bk : bv;
    float* Out        = (sel == 0) ? g_q : (sel == 1) ? g_k : g_v;
    const float* xnb = g_xn + (size_t)b * CHW;

    __shared__ float sA[2][128 * MST];
    __shared__ float sB[2][16 * KST];
    const int tid = threadIdx.x, warp = tid >> 5, lane = tid & 31;
    float acc[2][8][4] = {};

    auto load = [&](int s, int kc) {
        int k0 = kc * 16;
        int c = tid;
#pragma unroll
        for (int i = 0; i < 2; i++, c += 256) {
            int r = c >> 2, col = (c & 3) * 4;
            cp16(sptr(&sA[s][r * MST + col]), &Wsel[(m0 + r) * 256 + k0 + col], true);
        }
        c = tid;
#pragma unroll
        for (int i = 0; i < 2; i++, c += 256) {
            int r = c >> 5, col = (c & 31) * 4;
            cp16(sptr(&sB[s][r * KST + col]), &xnb[(size_t)(k0 + r) * HWP + n0 + col], true);
        }
    };

    const int NK = 16;
    load(0, 0); cp_commit();
    for (int kc = 0; kc < NK; kc++) {
        if (kc + 1 < NK) load((kc + 1) & 1, kc + 1);
        cp_commit();
        cp_wait<1>();
        __syncthreads();
        tile_mma<false, true>(sA[kc & 1], sB[kc & 1], acc, warp, lane);
        __syncthreads();
    }

    const int gr = lane >> 2, tg = lane & 3;
    const int m0w = 32 * (warp >> 1), n0w = 64 * (warp & 1);
#pragma unroll
    for (int mt = 0; mt < 2; mt++) {
        int mA = m0 + m0w + mt * 16 + gr;
        float bA = Bias[mA], bB = Bias[mA + 8];
#pragma unroll
        for (int nt = 0; nt < 8; nt++) {
            int n = n0 + n0w + nt * 8 + 2 * tg;
            *(float2*)&Out[(size_t)(b * CC + mA) * HWP + n] =
                make_float2(acc[mt][nt][0] + bA, acc[mt][nt][1] + bA);
            *(float2*)&Out[(size_t)(b * CC + mA + 8) * HWP + n] =
                make_float2(acc[mt][nt][2] + bB, acc[mt][nt][3] + bB);
        }
    }
}

// ---------------- 3) 2x2 average pool ----------------
__global__ void k_pool() {
    int idx = blockIdx.x * blockDim.x + threadIdx.x;
    if (idx >= BB * CC * A3) return;
    int t = idx % A3;
    int bc = idx / A3;
    int ty = t / TGD, tx = t % TGD;
    size_t base = (size_t)bc * HWP + (size_t)(2 * ty) * WW + 2 * tx;
    g_qp[idx] = 0.25f * (g_q[base] + g_q[base + 1] + g_q[base + WW] + g_q[base + WW + 1]);
    g_kp[idx] = 0.25f * (g_k[base] + g_k[base + 1] + g_k[base + WW] + g_k[base + WW + 1]);
    g_vp[idx] = 0.25f * (g_v[base] + g_v[base + 1] + g_v[base + WW] + g_v[base + WW + 1]);
}

// ---------------- 4) patch logits: A=q (k-major), B=k (k-major), split-K ----------------
__global__ void k_patt() {
    const int bz = blockIdx.z;
    const int b = bz >> 4, ks = bz & 15;
    const int m0 = blockIdx.y * 128, n0 = blockIdx.x * 128;
    const float* qb = g_q + (size_t)b * CHW;
    const float* kb = g_k + (size_t)b * CHW;

    __shared__ float sA[2][16 * KST];
    __shared__ float sB[2][16 * KST];
    const int tid = threadIdx.x, warp = tid >> 5, lane = tid & 31;
    float acc[2][8][4] = {};

    auto load = [&](int s, int kc) {
        int k0 = ks * 1024 + kc * 16;
        int c = tid;
#pragma unroll
        for (int i = 0; i < 2; i++, c += 256) {
            int r = c >> 5, col = (c & 31) * 4;
            bool vm = (m0 + col + 4 <= PP);
            bool vn = (n0 + col + 4 <= PP);
            const float* srcA = &qb[(size_t)(k0 + r) * PP + (vm ? m0 + col : 0)];
            const float* srcB = &kb[(size_t)(k0 + r) * PP + (vn ? n0 + col : 0)];
            cp16(sptr(&sA[s][r * KST + col]), srcA, vm);
            cp16(sptr(&sB[s][r * KST + col]), srcB, vn);
        }
    };

    const int NK = 64;
    load(0, 0); cp_commit();
    for (int kc = 0; kc < NK; kc++) {
        if (kc + 1 < NK) load((kc + 1) & 1, kc + 1);
        cp_commit();
        cp_wait<1>();
        __syncthreads();
        tile_mma<true, true>(sA[kc & 1], sB[kc & 1], acc, warp, lane);
        __syncthreads();
    }

    const float scale = 1.0f / 128.0f;
    const int gr = lane >> 2, tg = lane & 3;
    const int m0w = 32 * (warp >> 1), n0w = 64 * (warp & 1);
    float* ob = g_attp_part + (size_t)(ks * BB + b) * PP * PP;
#pragma unroll
    for (int mt = 0; mt < 2; mt++) {
#pragma unroll
        for (int nt = 0; nt < 8; nt++) {
            int n = n0 + n0w + nt * 8 + 2 * tg;
            if (n >= PP) continue;
            int mA = m0 + m0w + mt * 16 + gr;
            if (mA < PP)
                *(float2*)&ob[(size_t)mA * PP + n] =
                    make_float2(acc[mt][nt][0] * scale, acc[mt][nt][1] * scale);
            if (mA + 8 < PP)
                *(float2*)&ob[(size_t)(mA + 8) * PP + n] =
                    make_float2(acc[mt][nt][2] * scale, acc[mt][nt][3] * scale);
        }
    }
}

// ---------------- 5) patch softmax ----------------
__global__ void k_psm() {
    int row = blockIdx.x;
    __shared__ float srow[PP];
    __shared__ float red[256];
    int t = threadIdx.x;
    for (int q = t; q < PP; q += 256) {
        float s = 0.f;
#pragma unroll
        for (int ks = 0; ks < 16; ks++)
            s += g_attp_part[(size_t)ks * (BB * PP * PP) + (size_t)row * PP + q];
        srow[q] = s;
    }
    __syncthreads();
    float mx = -1e30f;
    for (int q = t; q < PP; q += 256) mx = fmaxf(mx, srow[q]);
    red[t] = mx;
    __syncthreads();
    for (int o = 128; o > 0; o >>= 1) { if (t < o) red[t] = fmaxf(red[t], red[t + o]); __syncthreads(); }
    mx = red[0];
    __syncthreads();
    float s = 0.f;
    for (int q = t; q < PP; q += 256) { float e = __expf(srow[q] - mx); srow[q] = e; s += e; }
    red[t] = s;
    __syncthreads();
    for (int o = 128; o > 0; o >>= 1) { if (t < o) red[t] += red[t + o]; __syncthreads(); }
    float inv = 1.0f / red[0];
    for (int q = t; q < PP; q += 256) g_attp[(size_t)row * PP + q] = srow[q] * inv;
}

// ---------------- 6) h_patch = V @ att^T: A=v (m-major), B=att (n-major) ----------------
__global__ void k_hpatch() {
    const int b = blockIdx.z;
    const int m0 = blockIdx.y * 128;
    const int n0 = blockIdx.x * 128;
    const float* vb = g_v + (size_t)b * CHW;
    const float* ab = g_attp + (size_t)b * PP * PP;

    __shared__ float sA[2][128 * MST];
    __shared__ float sB[2][128 * MST];
    const int tid = threadIdx.x, warp = tid >> 5, lane = tid & 31;
    float acc[2][8][4] = {};

    auto load = [&](int s, int kc) {
        int k0 = kc * 16;
        int c = tid;
#pragma unroll
        for (int i = 0; i < 2; i++, c += 256) {
            int r = c >> 2, col = (c & 3) * 4;
            bool vk = (k0 + col + 4 <= PP);
            cp16(sptr(&sA[s][r * MST + col]),
                 &vb[(size_t)(m0 + r) * PP + (vk ? k0 + col : 0)], vk);
            bool vb2 = vk && (n0 + r < PP);
            const float* srcB = vb2 ? &ab[(size_t)(n0 + r) * PP + k0 + col] : ab;
            cp16(sptr(&sB[s][r * MST + col]), srcB, vb2);
        }
    };

    const int NK = 13;   // ceil(196/16)
    load(0, 0); cp_commit();
    for (int kc = 0; kc < NK; kc++) {
        if (kc + 1 < NK) load((kc + 1) & 1, kc + 1);
        cp_commit();
        cp_wait<1>();
        __syncthreads();
        tile_mma<false, false>(sA[kc & 1], sB[kc & 1], acc, warp, lane);
        __syncthreads();
    }

    const int gr = lane >> 2, tg = lane & 3;
    const int m0w = 32 * (warp >> 1), n0w = 64 * (warp & 1);
    float* ob = g_hpatch + (size_t)b * CHW;
#pragma unroll
    for (int mt = 0; mt < 2; mt++) {
        int mA = m0 + m0w + mt * 16 + gr;
#pragma unroll
        for (int nt = 0; nt < 8; nt++) {
            int n = n0 + n0w + nt * 8 + 2 * tg;
            if (n >= PP) continue;
            *(float2*)&ob[(size_t)mA * PP + n] = make_float2(acc[mt][nt][0], acc[mt][nt][1]);
            *(float2*)&ob[(size_t)(mA + 8) * PP + n] = make_float2(acc[mt][nt][2], acc[mt][nt][3]);
        }
    }
}

// ---------------- 7) global logits: A=qp (k-major), B=kp (k-major) ----------------
__global__ void k_gatt() {
    const int b = blockIdx.z;
    const int m0 = blockIdx.y * 128, n0 = blockIdx.x * 128;
    const float* qb = g_qp + (size_t)b * CC * A3;
    const float* kb = g_kp + (size_t)b * CC * A3;

    __shared__ float sA[2][16 * KST];
    __shared__ float sB[2][16 * KST];
    const int tid = threadIdx.x, warp = tid >> 5, lane = tid & 31;
    float acc[2][8][4] = {};

    auto load = [&](int s, int kc) {
        int k0 = kc * 16;
        int c = tid;
#pragma unroll
        for (int i = 0; i < 2; i++, c += 256) {
            int r = c >> 5, col = (c & 31) * 4;
            bool vm = (m0 + col + 4 <= A3);
            bool vn = (n0 + col + 4 <= A3);
            cp16(sptr(&sA[s][r * KST + col]),
                 &qb[(size_t)(k0 + r) * A3 + (vm ? m0 + col : 0)], vm);
            cp16(sptr(&sB[s][r * KST + col]),
                 &kb[(size_t)(k0 + r) * A3 + (vn ? n0 + col : 0)], vn);
        }
    };

    const int NK = 16;
    load(0, 0); cp_commit();
    for (int kc = 0; kc < NK; kc++) {
        if (kc + 1 < NK) load((kc + 1) & 1, kc + 1);
        cp_commit();
        cp_wait<1>();
        __syncthreads();
        tile_mma<true, true>(sA[kc & 1], sB[kc & 1], acc, warp, lane);
        __syncthreads();
    }

    float* ob = g_attg + (size_t)b * A3 * A3;
    const int gr = lane >> 2, tg = lane & 3;
    const int m0w = 32 * (warp >> 1), n0w = 64 * (warp & 1);
#pragma unroll
    for (int mt = 0; mt < 2; mt++) {
        int mA = m0 + m0w + mt * 16 + gr;
#pragma unroll
        for (int nt = 0; nt < 8; nt++) {
            int n = n0 + n0w + nt * 8 + 2 * tg;
            if (n >= A3) continue;
            if (mA < A3)
                *(float2*)&ob[(size_t)mA * A3 + n] =
                    make_float2(acc[mt][nt][0] * 0.0625f, acc[mt][nt][1] * 0.0625f);
            if (mA + 8 < A3)
                *(float2*)&ob[(size_t)(mA + 8) * A3 + n] =
                    make_float2(acc[mt][nt][2] * 0.0625f, acc[mt][nt][3] * 0.0625f);
        }
    }
}

// ---------------- 8) global softmax ----------------
__global__ void k_gsm() {
    float* r = g_attg + (size_t)blockIdx.x * A3;
    __shared__ float srow[A3];
    __shared__ float red[256];
    int t = threadIdx.x;
    float mx = -1e30f;
    for (int i = t; i < A3; i += 256) { float v = r[i]; srow[i] = v; mx = fmaxf(mx, v); }
    red[t] = mx;
    __syncthreads();
    for (int o = 128; o > 0; o >>= 1) { if (t < o) red[t] = fmaxf(red[t], red[t + o]); __syncthreads(); }
    mx = red[0];
    __syncthreads();
    float s = 0.f;
    for (int i = t; i < A3; i += 256) { float e = __expf(srow[i] - mx); srow[i] = e; s += e; }
    red[t] = s;
    __syncthreads();
    for (int o = 128; o > 0; o >>= 1) { if (t < o) red[t] += red[t + o]; __syncthreads(); }
    float inv = 1.0f / red[0];
    for (int i = t; i < A3; i += 256) r[i] = srow[i] * inv;
}

// ---------------- 9) h_glob = Vp @ att^T: A=vp (m-major), B=attg (n-major) ----------------
__global__ void k_hglob() {
    const int b = blockIdx.z;
    const int m0 = blockIdx.y * 128;
    const int n0 = blockIdx.x * 128;
    const float* vb = g_vp + (size_t)b * CC * A3;
    const float* ab = g_attg + (size_t)b * A3 * A3;

    __shared__ float sA[2][128 * MST];
    __shared__ float sB[2][128 * MST];
    const int tid = threadIdx.x, warp = tid >> 5, lane = tid & 31;
    float acc[2][8][4] = {};

    auto load = [&](int s, int kc) {
        int k0 = kc * 16;
        int c = tid;
#pragma unroll
        for (int i = 0; i < 2; i++, c += 256) {
            int r = c >> 2, col = (c & 3) * 4;
            cp16(sptr(&sA[s][r * MST + col]), &vb[(size_t)(m0 + r) * A3 + k0 + col], true);
            bool vn = (n0 + r < A3);
            const float* srcB = vn ? &ab[(size_t)(n0 + r) * A3 + k0 + col] : ab;
            cp16(sptr(&sB[s][r * MST + col]), srcB, vn);
        }
    };

    const int NK = 196;
    load(0, 0); cp_commit();
    for (int kc = 0; kc < NK; kc++) {
        if (kc + 1 < NK) load((kc + 1) & 1, kc + 1);
        cp_commit();
        cp_wait<1>();
        __syncthreads();
        tile_mma<false, false>(sA[kc & 1], sB[kc & 1], acc, warp, lane);
        __syncthreads();
    }

    float* ob = g_hglob + (size_t)b * CC * A3;
    const int gr = lane >> 2, tg = lane & 3;
    const int m0w = 32 * (warp >> 1), n0w = 64 * (warp & 1);
#pragma unroll
    for (int mt = 0; mt < 2; mt++) {
        int mA = m0 + m0w + mt * 16 + gr;
#pragma unroll
        for (int nt = 0; nt < 8; nt++) {
            int n = n0 + n0w + nt * 8 + 2 * tg;
            if (n >= A3) continue;
            *(float2*)&ob[(size_t)mA * A3 + n] = make_float2(acc[mt][nt][0], acc[mt][nt][1]);
            *(float2*)&ob[(size_t)(mA + 8) * A3 + n] = make_float2(acc[mt][nt][2], acc[mt][nt][3]);
        }
    }
}

// ---------------- 10) combine ----------------
__global__ void k_comb() {
    int idx = blockIdx.x * blockDim.x + threadIdx.x;
    if (idx >= BB * CHW) return;
    int hw = idx % HWP;
    int bc = idx / HWP;
    int i = hw / WW, j = hw % WW;
    float sy = 0.5f * i - 0.25f;
    int y0 = (int)floorf(sy);
    float fy = sy - (float)y0;
    int y0c = max(y0, 0), y1c = min(y0 + 1, TGD - 1);
    float sx = 0.5f * j - 0.25f;
    int x0 = (int)floorf(sx);
    float fx = sx - (float)x0;
    int x0c = max(x0, 0), x1c = min(x0 + 1, TGD - 1);
    const float* hg = g_hglob + (size_t)bc * A3;
    float v00 = hg[y0c * TGD + x0c], v01 = hg[y0c * TGD + x1c];
    float v10 = hg[y1c * TGD + x0c], v11 = hg[y1c * TGD + x1c];
    float bil = (1.f - fy) * ((1.f - fx) * v00 + fx * v01) +
                fy * ((1.f - fx) * v10 + fx * v11);
    g_h[idx] = 0.75f * g_hpatch[idx] + 0.25f * bil;
}

// ---------------- 11) proj + residual: A=wp (m-major), B=h (k-major) ----------------
__global__ void k_proj(const float* __restrict__ x, const float* __restrict__ wp,
                       float* __restrict__ out) {
    const int b = blockIdx.z;
    const int m0 = blockIdx.y * 128;
    const int n0 = blockIdx.x * 128;
    const float* hb = g_h + (size_t)b * CHW;

    __shared__ float sA[2][128 * MST];
    __shared__ float sB[2][16 * KST];
    const int tid = threadIdx.x, warp = tid >> 5, lane = tid & 31;
    float acc[2][8][4] = {};

    auto load = [&](int s, int kc) {
        int k0 = kc * 16;
        int c = tid;
#pragma unroll
        for (int i = 0; i < 2; i++, c += 256) {
            int r = c >> 2, col = (c & 3) * 4;
            cp16(sptr(&sA[s][r * MST + col]), &wp[(m0 + r) * 256 + k0 + col], true);
        }
        c = tid;
#pragma unroll
        for (int i = 0; i < 2; i++, c += 256) {
            int r = c >> 5, col = (c & 31) * 4;
            cp16(sptr(&sB[s][r * KST + col]), &hb[(size_t)(k0 + r) * HWP + n0 + col], true);
        }
    };

    const int NK = 16;
    load(0, 0); cp_commit();
    for (int kc = 0; kc < NK; kc++) {
        if (kc + 1 < NK) load((kc + 1) & 1, kc + 1);
        cp_commit();
        cp_wait<1>();
        __syncthreads();
        tile_mma<false, true>(sA[kc & 1], sB[kc & 1], acc, warp, lane);
        __syncthreads();
    }

    const int gr = lane >> 2, tg = lane & 3;
    const int m0w = 32 * (warp >> 1), n0w = 64 * (warp & 1);
#pragma unroll
    for (int mt = 0; mt < 2; mt++) {
        int mA = m0 + m0w + mt * 16 + gr;
#pragma unroll
        for (int nt = 0; nt < 8; nt++) {
            int n = n0 + n0w + nt * 8 + 2 * tg;
            size_t o0 = (size_t)b * CHW + (size_t)mA * HWP + n;
            size_t o1 = (size_t)b * CHW + (size_t)(mA + 8) * HWP + n;
            float2 x0 = *(const float2*)&x[o0];
            float2 x1 = *(const float2*)&x[o1];
            *(float2*)&out[o0] = make_float2(x0.x + acc[mt][nt][0], x0.y + acc[mt][nt][1]);
            *(float2*)&out[o1] = make_float2(x1.x + acc[mt][nt][2], x1.y + acc[mt][nt][3]);
        }
    }
}

// ---------------- launch ----------------
extern "C" void kernel_launch(void* const* d_in, const int* in_sizes, int n_in,
                              void* d_out, int out_size) {
    const float* x   = (const float*)d_in[0];
    const float* gnw = (const float*)d_in[1];
    const float* gnb = (const float*)d_in[2];
    const float* wq  = (const float*)d_in[3];
    const float* bq  = (const float*)d_in[4];
    const float* wk  = (const float*)d_in[5];
    const float* bk  = (const float*)d_in[6];
    const float* wv  = (const float*)d_in[7];
    const float* bv  = (const float*)d_in[8];
    const float* wp  = (const float*)d_in[9];
    float* out = (float*)d_out;

    k_gn_stats<<<dim3(64, 8), 256>>>(x);
    k_gn_reduce<<<8, 64>>>();
    k_xn<<<(BB * CHW / 4 + 255) / 256, 256>>>(x, gnw, gnb);
    k_qkv<<<dim3(98, 6, 8), 256>>>(wq, bq, wk, bk, wv, bv);
    k_pool<<<(BB * CC * A3 + 255) / 256, 256>>>();
    k_patt<<<dim3(2, 2, 128), 256>>>();
    k_psm<<<BB * PP, 256>>>();
    k_hpatch<<<dim3(2, 128, 8), 256>>>();
    k_gatt<<<dim3(25, 25, 8), 256>>>();
    k_gsm<<<BB * A3, 256>>>();
    k_hglob<<<dim3(25, 2, 8), 256>>>();
    k_comb<<<(BB * CHW + 255) / 256, 256>>>();
    k_proj<<<dim3(98, 2, 8), 256>>>(x, wp, out);
}

// round 7
// speedup vs baseline: 5.8420x; 1.6215x over previous
#include <cuda_runtime.h>
#include <cuda_bf16.h>
#include <math.h>

typedef __nv_bfloat16 bf16;

// ---------------- problem constants ----------------
#define BB   8
#define CC   256
#define HH   112
#define WW   112
#define HWP  12544
#define CHW  3211264
#define PP   196
#define A3   3136
#define TGD  56

#define KS   136                // k-major smem stride (bf16 elems), [32][136]
#define MS   40                 // m/n-major smem stride (bf16 elems), [128][40]
#define APR  224                // attp padded row stride (zeros beyond 195)

// ---------------- scratch ----------------
__device__ bf16  g_xn[BB * CHW + 64];
__device__ bf16  g_q[BB * CHW + 64];
__device__ bf16  g_k[BB * CHW + 64];
__device__ bf16  g_v[BB * CHW + 64];
__device__ bf16  g_qp[BB * CC * A3 + 64];
__device__ bf16  g_kp[BB * CC * A3 + 64];
__device__ bf16  g_vp[BB * CC * A3 + 64];
__device__ float g_attp_part[16 * BB * PP * PP];
__device__ bf16  g_attp[BB * 256 * APR];            // zero-init pads
__device__ bf16  g_hpatch[BB * CHW + 64];
__device__ bf16  g_attg[(size_t)BB * A3 * A3 + 64];
__device__ bf16  g_hglob[BB * CC * A3 + 64];
__device__ bf16  g_h[BB * CHW + 64];
__device__ bf16  g_wb[4 * CC * CC];
__device__ float g_spart[BB * 64 * 2];
__device__ float g_stats[BB * 2];

// ---------------- primitives ----------------
__device__ __forceinline__ unsigned sptr(const void* p) {
    return (unsigned)__cvta_generic_to_shared(p);
}
__device__ __forceinline__ void cp16(unsigned dst, const void* src, bool v) {
    asm volatile("cp.async.cg.shared.global [%0], [%1], 16, %2;"
                 :: "r"(dst), "l"(src), "r"(v ? 16 : 0));
}
__device__ __forceinline__ void cp8(unsigned dst, const void* src) {
    asm volatile("cp.async.ca.shared.global [%0], [%1], 8;" :: "r"(dst), "l"(src));
}
__device__ __forceinline__ void cp_commit() { asm volatile("cp.async.commit_group;"); }
template <int N>
__device__ __forceinline__ void cp_wait() { asm volatile("cp.async.wait_group %0;" :: "n"(N)); }

__device__ __forceinline__ void ldsm4(unsigned* r, unsigned addr) {
    asm volatile("ldmatrix.sync.aligned.m8n8.x4.shared.b16 {%0,%1,%2,%3}, [%4];"
                 : "=r"(r[0]), "=r"(r[1]), "=r"(r[2]), "=r"(r[3]) : "r"(addr));
}
__device__ __forceinline__ void ldsm4t(unsigned* r, unsigned addr) {
    asm volatile("ldmatrix.sync.aligned.m8n8.x4.trans.shared.b16 {%0,%1,%2,%3}, [%4];"
                 : "=r"(r[0]), "=r"(r[1]), "=r"(r[2]), "=r"(r[3]) : "r"(addr));
}
__device__ __forceinline__ void mma16(float* c, const unsigned* a, unsigned b0, unsigned b1) {
    asm volatile(
        "mma.sync.aligned.m16n8k16.row.col.f32.bf16.bf16.f32 "
        "{%0,%1,%2,%3}, {%4,%5,%6,%7}, {%8,%9}, {%0,%1,%2,%3};"
        : "+f"(c[0]), "+f"(c[1]), "+f"(c[2]), "+f"(c[3])
        : "r"(a[0]), "r"(a[1]), "r"(a[2]), "r"(a[3]), "r"(b0), "r"(b1));
}
__device__ __forceinline__ unsigned packbf(float x, float y) {
    __nv_bfloat162 t = __floats2bfloat162_rn(x, y);
    return *(unsigned*)&t;
}

// 128x128 block tile, 8 warps (warp w -> m-slab 32*(w>>1), n-slab 64*(w&1)), k-chunk 32.
template <bool AT, bool BT>
__device__ __forceinline__ void tile_mma16(const bf16* As, const bf16* Bs,
                                           float (&acc)[2][8][4], int warp, int lane) {
    const int m0w = 32 * (warp >> 1), n0w = 64 * (warp & 1);
    const int j = lane >> 3, i = lane & 7;
#pragma unroll
    for (int kt = 0; kt < 2; kt++) {
        const int k0 = kt * 16;
        unsigned a[2][4];
#pragma unroll
        for (int mt = 0; mt < 2; mt++) {
            if (AT) {
                const bf16* p = As + (size_t)(k0 + (j >> 1) * 8 + i) * KS
                              + m0w + mt * 16 + (j & 1) * 8;
                ldsm4t(a[mt], sptr(p));
            } else {
                const bf16* p = As + (size_t)(m0w + mt * 16 + (j & 1) * 8 + i) * MS
                              + k0 + (j >> 1) * 8;
                ldsm4(a[mt], sptr(p));
            }
        }
#pragma unroll
        for (int ng = 0; ng < 4; ng++) {
            unsigned b[4];
            if (BT) {
                const bf16* p = Bs + (size_t)(k0 + (j & 1) * 8 + i) * KS
                              + n0w + ng * 16 + (j >> 1) * 8;
                ldsm4t(b, sptr(p));
            } else {
                const bf16* p = Bs + (size_t)(n0w + ng * 16 + (j >> 1) * 8 + i) * MS
                              + k0 + (j & 1) * 8;
                ldsm4(b, sptr(p));
            }
            mma16(acc[0][ng * 2],     a[0], b[0], b[1]);
            mma16(acc[0][ng * 2 + 1], a[0], b[2], b[3]);
            mma16(acc[1][ng * 2],     a[1], b[0], b[1]);
            mma16(acc[1][ng * 2 + 1], a[1], b[2], b[3]);
        }
    }
}

// ---------------- 0) weights -> bf16 ----------------
__global__ void k_wprep(const float* __restrict__ wq, const float* __restrict__ wk,
                        const float* __restrict__ wv, const float* __restrict__ wp) {
    int idx = blockIdx.x * blockDim.x + threadIdx.x;
    if (idx >= 4 * CC * CC) return;
    int w = idx >> 16, r = idx & 65535;
    const float* src = (w == 0) ? wq : (w == 1) ? wk : (w == 2) ? wv : wp;
    g_wb[idx] = __float2bfloat16(src[r]);
}

// ---------------- 1) GroupNorm stats ----------------
__global__ void k_gn_stats(const float* __restrict__ x) {
    int b = blockIdx.y;
    const float* xb = x + (size_t)b * CHW;
    float s1 = 0.f, s2 = 0.f;
    for (int i = blockIdx.x * blockDim.x + threadIdx.x; i < CHW;
         i += gridDim.x * blockDim.x) {
        float v = xb[i];
        s1 += v; s2 += v * v;
    }
    __shared__ float sm1[256], sm2[256];
    int t = threadIdx.x;
    sm1[t] = s1; sm2[t] = s2;
    __syncthreads();
    for (int o = 128; o > 0; o >>= 1) {
        if (t < o) { sm1[t] += sm1[t + o]; sm2[t] += sm2[t + o]; }
        __syncthreads();
    }
    if (t == 0) {
        g_spart[(b * 64 + blockIdx.x) * 2 + 0] = sm1[0];
        g_spart[(b * 64 + blockIdx.x) * 2 + 1] = sm2[0];
    }
}

__global__ void k_gn_reduce() {
    int b = blockIdx.x, t = threadIdx.x;
    __shared__ float sm1[64], sm2[64];
    sm1[t] = g_spart[(b * 64 + t) * 2 + 0];
    sm2[t] = g_spart[(b * 64 + t) * 2 + 1];
    __syncthreads();
    for (int o = 32; o > 0; o >>= 1) {
        if (t < o) { sm1[t] += sm1[t + o]; sm2[t] += sm2[t + o]; }
        __syncthreads();
    }
    if (t == 0) {
        g_stats[b * 2 + 0] = sm1[0];
        g_stats[b * 2 + 1] = sm2[0];
    }
}

// ---------------- 1b) apply GN -> bf16 ----------------
__global__ void k_xn(const float* __restrict__ x,
                     const float* __restrict__ gnw, const float* __restrict__ gnb) {
    int idx = blockIdx.x * blockDim.x + threadIdx.x;
    if (idx >= BB * CHW / 4) return;
    int fi = idx * 4;
    int b = fi / CHW;
    int rem = fi - b * CHW;
    int c = rem / HWP;
    float s1 = g_stats[b * 2], s2 = g_stats[b * 2 + 1];
    const float invN = 1.0f / (float)CHW;
    float mu = s1 * invN;
    float rstd = rsqrtf(s2 * invN - mu * mu + 1e-5f);
    float sc = rstd * gnw[c];
    float sh = gnb[c] - mu * sc;
    float4 v = *(const float4*)&x[fi];
    bf16* o = &g_xn[fi];
    *(__nv_bfloat162*)o       = __floats2bfloat162_rn(v.x * sc + sh, v.y * sc + sh);
    *(__nv_bfloat162*)(o + 2) = __floats2bfloat162_rn(v.z * sc + sh, v.w * sc + sh);
}

// ---------------- 2) QKV: A=W bf16 m-major, B=xn bf16 k-major ----------------
__global__ void k_qkv(const float* __restrict__ bq, const float* __restrict__ bk,
                      const float* __restrict__ bv) {
    const int b = blockIdx.z;
    const int n0 = blockIdx.x * 128;
    const int m0g = blockIdx.y * 128;
    const int sel = m0g >> 8;
    const int m0 = m0g & 255;
    const bf16* Wsel = g_wb + sel * CC * CC;
    const float* Bias = (sel == 0) ? bq : (sel == 1) ? bk : bv;
    bf16* Out         = (sel == 0) ? g_q : (sel == 1) ? g_k : g_v;
    const bf16* xnb = g_xn + (size_t)b * CHW;

    __shared__ bf16 sA[2][128 * MS];
    __shared__ bf16 sB[2][32 * KS];
    const int tid = threadIdx.x, warp = tid >> 5, lane = tid & 31;
    float acc[2][8][4] = {};

    auto load = [&](int s, int kc) {
        int k0 = kc * 32;
#pragma unroll
        for (int i = 0; i < 2; i++) {
            int idx = tid + i * 256;
            int r = idx >> 2, seg = idx & 3;
            cp16(sptr(&sA[s][r * MS + seg * 8]), Wsel + (m0 + r) * CC + k0 + seg * 8, true);
        }
#pragma unroll
        for (int i = 0; i < 2; i++) {
            int idx = tid + i * 256;
            int r = idx >> 4, seg = idx & 15;
            cp16(sptr(&sB[s][r * KS + seg * 8]), xnb + (size_t)(k0 + r) * HWP + n0 + seg * 8, true);
        }
    };

    const int NK = 8;
    load(0, 0); cp_commit();
    for (int kc = 0; kc < NK; kc++) {
        if (kc + 1 < NK) load((kc + 1) & 1, kc + 1);
        cp_commit();
        cp_wait<1>();
        __syncthreads();
        tile_mma16<false, true>(sA[kc & 1], sB[kc & 1], acc, warp, lane);
        __syncthreads();
    }

    const int gr = lane >> 2, tg = lane & 3;
    const int m0w = 32 * (warp >> 1), n0w = 64 * (warp & 1);
#pragma unroll
    for (int mt = 0; mt < 2; mt++) {
        int mA = m0 + m0w + mt * 16 + gr;
        float bA = Bias[mA], bB = Bias[mA + 8];
#pragma unroll
        for (int nt = 0; nt < 8; nt++) {
            int n = n0 + n0w + nt * 8 + 2 * tg;
            *(unsigned*)&Out[(size_t)(b * CC + mA) * HWP + n] =
                packbf(acc[mt][nt][0] + bA, acc[mt][nt][1] + bA);
            *(unsigned*)&Out[(size_t)(b * CC + mA + 8) * HWP + n] =
                packbf(acc[mt][nt][2] + bB, acc[mt][nt][3] + bB);
        }
    }
}

// ---------------- 3) 2x2 average pool ----------------
__global__ void k_pool() {
    int idx = blockIdx.x * blockDim.x + threadIdx.x;
    if (idx >= BB * CC * A3) return;
    int t = idx % A3;
    int bc = idx / A3;
    int ty = t / TGD, tx = t % TGD;
    size_t base = (size_t)bc * HWP + (size_t)(2 * ty) * WW + 2 * tx;
    g_qp[idx] = __float2bfloat16(0.25f * (__bfloat162float(g_q[base]) + __bfloat162float(g_q[base + 1]) +
                                          __bfloat162float(g_q[base + WW]) + __bfloat162float(g_q[base + WW + 1])));
    g_kp[idx] = __float2bfloat16(0.25f * (__bfloat162float(g_k[base]) + __bfloat162float(g_k[base + 1]) +
                                          __bfloat162float(g_k[base + WW]) + __bfloat162float(g_k[base + WW + 1])));
    g_vp[idx] = __float2bfloat16(0.25f * (__bfloat162float(g_v[base]) + __bfloat162float(g_v[base + 1]) +
                                          __bfloat162float(g_v[base + WW]) + __bfloat162float(g_v[base + WW + 1])));
}

// ---------------- 4) patch logits: A=q, B=k, both k-major; split-K=16 ----------------
// PP rows are 392 B (mod 16 = 8) -> use 2x cp8 (row base mod 8 == 0 always).
__global__ void k_patt() {
    const int bz = blockIdx.z;
    const int b = bz >> 4, ks = bz & 15;
    const int m0 = blockIdx.y * 128, n0 = blockIdx.x * 128;
    const bf16* qb = g_q + (size_t)b * CHW;
    const bf16* kb = g_k + (size_t)b * CHW;

    __shared__ bf16 sA[2][32 * KS];
    __shared__ bf16 sB[2][32 * KS];
    const int tid = threadIdx.x, warp = tid >> 5, lane = tid & 31;
    float acc[2][8][4] = {};

    auto load = [&](int s, int kc) {
        int k0 = ks * 1024 + kc * 32;
#pragma unroll
        for (int i = 0; i < 4; i++) {
            int idx = tid + i * 256;
            int tile = idx >> 9, rem = idx & 511;
            int r = rem >> 4, seg = rem & 15;
            int base0 = tile ? n0 : m0;
            const bf16* gsrc = tile ? kb : qb;
            bf16* st = tile ? &sB[s][0] : &sA[s][0];
            int gm = base0 + seg * 8;
            unsigned dst = sptr(st + r * KS + seg * 8);
            const bf16* sp = gsrc + (size_t)(k0 + r) * PP + gm;
            if (gm + 8 <= PP) {                 // full 8 elems via 2x cp8
                cp8(dst, sp);
                cp8(dst + 8, sp + 4);
            } else if (gm < PP) {               // gm==192: 4 valid elems
                cp8(dst, sp);                   // tail garbage -> discarded outputs
            } else {
                cp16(dst, gsrc, false);         // zero-fill (dst/src aligned)
            }
        }
    };

    const int NK = 32;
    load(0, 0); cp_commit();
    for (int kc = 0; kc < NK; kc++) {
        if (kc + 1 < NK) load((kc + 1) & 1, kc + 1);
        cp_commit();
        cp_wait<1>();
        __syncthreads();
        tile_mma16<true, true>(sA[kc & 1], sB[kc & 1], acc, warp, lane);
        __syncthreads();
    }

    const float scale = 1.0f / 128.0f;
    const int gr = lane >> 2, tg = lane & 3;
    const int m0w = 32 * (warp >> 1), n0w = 64 * (warp & 1);
    float* ob = g_attp_part + (size_t)(ks * BB + b) * PP * PP;
#pragma unroll
    for (int mt = 0; mt < 2; mt++) {
#pragma unroll
        for (int nt = 0; nt < 8; nt++) {
            int n = n0 + n0w + nt * 8 + 2 * tg;
            if (n >= PP) continue;
            int mA = m0 + m0w + mt * 16 + gr;
            if (mA < PP)
                *(float2*)&ob[(size_t)mA * PP + n] =
                    make_float2(acc[mt][nt][0] * scale, acc[mt][nt][1] * scale);
            if (mA + 8 < PP)
                *(float2*)&ob[(size_t)(mA + 8) * PP + n] =
                    make_float2(acc[mt][nt][2] * scale, acc[mt][nt][3] * scale);
        }
    }
}

// ---------------- 5) patch softmax -> bf16 padded attp ----------------
__global__ void k_psm() {
    int row = blockIdx.x;
    int b = row / PP, p = row % PP;
    __shared__ float srow[PP];
    __shared__ float red[256];
    int t = threadIdx.x;
    for (int q = t; q < PP; q += 256) {
        float s = 0.f;
#pragma unroll
        for (int ks = 0; ks < 16; ks++)
            s += g_attp_part[(size_t)ks * (BB * PP * PP) + (size_t)row * PP + q];
        srow[q] = s;
    }
    __syncthreads();
    float mx = -1e30f;
    for (int q = t; q < PP; q += 256) mx = fmaxf(mx, srow[q]);
    red[t] = mx;
    __syncthreads();
    for (int o = 128; o > 0; o >>= 1) { if (t < o) red[t] = fmaxf(red[t], red[t + o]); __syncthreads(); }
    mx = red[0];
    __syncthreads();
    float s = 0.f;
    for (int q = t; q < PP; q += 256) { float e = __expf(srow[q] - mx); srow[q] = e; s += e; }
    red[t] = s;
    __syncthreads();
    for (int o = 128; o > 0; o >>= 1) { if (t < o) red[t] += red[t + o]; __syncthreads(); }
    float inv = 1.0f / red[0];
    bf16* ob = g_attp + ((size_t)b * 256 + p) * APR;
    for (int q = t; q < PP; q += 256) ob[q] = __float2bfloat16(srow[q] * inv);
}

// ---------------- 6) h_patch = V @ att^T: A=v m-major (392B rows -> cp8), B=attp n-major ----------------
__global__ void k_hpatch() {
    const int b = blockIdx.z;
    const int m0 = blockIdx.y * 128;
    const int n0 = blockIdx.x * 128;
    const bf16* vb = g_v + (size_t)b * CHW;
    const bf16* apb = g_attp + (size_t)b * 256 * APR;

    __shared__ bf16 sA[2][128 * MS];
    __shared__ bf16 sB[2][128 * MS];
    const int tid = threadIdx.x, warp = tid >> 5, lane = tid & 31;
    float acc[2][8][4] = {};

    auto load = [&](int s, int kc) {
        int k0 = kc * 32;
#pragma unroll
        for (int i = 0; i < 4; i++) {
            int idx = tid + i * 256;
            int tile = idx >> 9, rem = idx & 511;
            int r = rem >> 2, seg = rem & 3;
            if (tile == 0) {
                // v rows stride 392 B: 2x cp8 (8B aligned). k-tail spills -> B zeros those k.
                unsigned dst = sptr(&sA[s][r * MS + seg * 8]);
                const bf16* sp = vb + (size_t)(m0 + r) * PP + k0 + seg * 8;
                cp8(dst, sp);
                cp8(dst + 8, sp + 4);
            } else {
                cp16(sptr(&sB[s][r * MS + seg * 8]),
                     apb + (size_t)(n0 + r) * APR + k0 + seg * 8, true);
            }
        }
    };

    const int NK = 7;
    load(0, 0); cp_commit();
    for (int kc = 0; kc < NK; kc++) {
        if (kc + 1 < NK) load((kc + 1) & 1, kc + 1);
        cp_commit();
        cp_wait<1>();
        __syncthreads();
        tile_mma16<false, false>(sA[kc & 1], sB[kc & 1], acc, warp, lane);
        __syncthreads();
    }

    const int gr = lane >> 2, tg = lane & 3;
    const int m0w = 32 * (warp >> 1), n0w = 64 * (warp & 1);
    bf16* ob = g_hpatch + (size_t)b * CHW;
#pragma unroll
    for (int mt = 0; mt < 2; mt++) {
        int mA = m0 + m0w + mt * 16 + gr;
#pragma unroll
        for (int nt = 0; nt < 8; nt++) {
            int n = n0 + n0w + nt * 8 + 2 * tg;
            if (n >= PP) continue;
            *(unsigned*)&ob[(size_t)mA * PP + n] = packbf(acc[mt][nt][0], acc[mt][nt][1]);
            *(unsigned*)&ob[(size_t)(mA + 8) * PP + n] = packbf(acc[mt][nt][2], acc[mt][nt][3]);
        }
    }
}

// ---------------- 7) global logits (bf16 out): A=qp, B=kp k-major ----------------
__global__ void k_gatt() {
    const int b = blockIdx.z;
    const int m0 = blockIdx.y * 128, n0 = blockIdx.x * 128;
    const bf16* qb = g_qp + (size_t)b * CC * A3;
    const bf16* kb = g_kp + (size_t)b * CC * A3;

    __shared__ bf16 sA[2][32 * KS];
    __shared__ bf16 sB[2][32 * KS];
    const int tid = threadIdx.x, warp = tid >> 5, lane = tid & 31;
    float acc[2][8][4] = {};

    auto load = [&](int s, int kc) {
        int k0 = kc * 32;
#pragma unroll
        for (int i = 0; i < 4; i++) {
            int idx = tid + i * 256;
            int tile = idx >> 9, rem = idx & 511;
            int r = rem >> 4, seg = rem & 15;
            int base0 = tile ? n0 : m0;
            const bf16* gsrc = tile ? kb : qb;
            bf16* st = tile ? &sB[s][0] : &sA[s][0];
            int gm = base0 + seg * 8;
            bool v = (gm < A3);
            cp16(sptr(st + r * KS + seg * 8),
                 gsrc + (size_t)(k0 + r) * A3 + (v ? gm : 0), v);
        }
    };

    const int NK = 8;
    load(0, 0); cp_commit();
    for (int kc = 0; kc < NK; kc++) {
        if (kc + 1 < NK) load((kc + 1) & 1, kc + 1);
        cp_commit();
        cp_wait<1>();
        __syncthreads();
        tile_mma16<true, true>(sA[kc & 1], sB[kc & 1], acc, warp, lane);
        __syncthreads();
    }

    bf16* ob = g_attg + (size_t)b * A3 * A3;
    const int gr = lane >> 2, tg = lane & 3;
    const int m0w = 32 * (warp >> 1), n0w = 64 * (warp & 1);
#pragma unroll
    for (int mt = 0; mt < 2; mt++) {
        int mA = m0 + m0w + mt * 16 + gr;
#pragma unroll
        for (int nt = 0; nt < 8; nt++) {
            int n = n0 + n0w + nt * 8 + 2 * tg;
            if (n >= A3) continue;
            if (mA < A3)
                *(unsigned*)&ob[(size_t)mA * A3 + n] =
                    packbf(acc[mt][nt][0] * 0.0625f, acc[mt][nt][1] * 0.0625f);
            if (mA + 8 < A3)
                *(unsigned*)&ob[(size_t)(mA + 8) * A3 + n] =
                    packbf(acc[mt][nt][2] * 0.0625f, acc[mt][nt][3] * 0.0625f);
        }
    }
}

// ---------------- 8) global softmax, in-place bf16 ----------------
__global__ void k_gsm() {
    bf16* r = g_attg + (size_t)blockIdx.x * A3;
    __shared__ float srow[A3];
    __shared__ float red[256];
    int t = threadIdx.x;
    float mx = -1e30f;
    for (int i = t; i < A3; i += 256) {
        float v = __bfloat162float(r[i]);
        srow[i] = v;
        mx = fmaxf(mx, v);
    }
    red[t] = mx;
    __syncthreads();
    for (int o = 128; o > 0; o >>= 1) { if (t < o) red[t] = fmaxf(red[t], red[t + o]); __syncthreads(); }
    mx = red[0];
    __syncthreads();
    float s = 0.f;
    for (int i = t; i < A3; i += 256) { float e = __expf(srow[i] - mx); srow[i] = e; s += e; }
    red[t] = s;
    __syncthreads();
    for (int o = 128; o > 0; o >>= 1) { if (t < o) red[t] += red[t + o]; __syncthreads(); }
    float inv = 1.0f / red[0];
    for (int i = t; i < A3; i += 256) r[i] = __float2bfloat16(srow[i] * inv);
}

// ---------------- 9) h_glob = Vp @ att^T: A=vp m-major, B=attg n-major ----------------
__global__ void k_hglob() {
    const int b = blockIdx.z;
    const int m0 = blockIdx.y * 128;
    const int n0 = blockIdx.x * 128;
    const bf16* vb = g_vp + (size_t)b * CC * A3;
    const bf16* ab = g_attg + (size_t)b * A3 * A3;

    __shared__ bf16 sA[2][128 * MS];
    __shared__ bf16 sB[2][128 * MS];
    const int tid = threadIdx.x, warp = tid >> 5, lane = tid & 31;
    float acc[2][8][4] = {};

    auto load = [&](int s, int kc) {
        int k0 = kc * 32;
#pragma unroll
        for (int i = 0; i < 4; i++) {
            int idx = tid + i * 256;
            int tile = idx >> 9, rem = idx & 511;
            int r = rem >> 2, seg = rem & 3;
            if (tile == 0) {
                cp16(sptr(&sA[s][r * MS + seg * 8]),
                     vb + (size_t)(m0 + r) * A3 + k0 + seg * 8, true);
            } else {
                bool vn = (n0 + r) < A3;
                cp16(sptr(&sB[s][r * MS + seg * 8]),
                     ab + (vn ? (size_t)(n0 + r) * A3 + k0 + seg * 8 : 0), vn);
            }
        }
    };

    const int NK = 98;
    load(0, 0); cp_commit();
    for (int kc = 0; kc < NK; kc++) {
        if (kc + 1 < NK) load((kc + 1) & 1, kc + 1);
        cp_commit();
        cp_wait<1>();
        __syncthreads();
        tile_mma16<false, false>(sA[kc & 1], sB[kc & 1], acc, warp, lane);
        __syncthreads();
    }

    bf16* ob = g_hglob + (size_t)b * CC * A3;
    const int gr = lane >> 2, tg = lane & 3;
    const int m0w = 32 * (warp >> 1), n0w = 64 * (warp & 1);
#pragma unroll
    for (int mt = 0; mt < 2; mt++) {
        int mA = m0 + m0w + mt * 16 + gr;
#pragma unroll
        for (int nt = 0; nt < 8; nt++) {
            int n = n0 + n0w + nt * 8 + 2 * tg;
            if (n >= A3) continue;
            *(unsigned*)&ob[(size_t)mA * A3 + n] = packbf(acc[mt][nt][0], acc[mt][nt][1]);
            *(unsigned*)&ob[(size_t)(mA + 8) * A3 + n] = packbf(acc[mt][nt][2], acc[mt][nt][3]);
        }
    }
}

// ---------------- 10) combine -> bf16 h ----------------
__global__ void k_comb() {
    int idx = blockIdx.x * blockDim.x + threadIdx.x;
    if (idx >= BB * CHW) return;
    int hw = idx % HWP;
    int bc = idx / HWP;
    int i = hw / WW, j = hw % WW;
    float sy = 0.5f * i - 0.25f;
    int y0 = (int)floorf(sy);
    float fy = sy - (float)y0;
    int y0c = max(y0, 0), y1c = min(y0 + 1, TGD - 1);
    float sx = 0.5f * j - 0.25f;
    int x0 = (int)floorf(sx);
    float fx = sx - (float)x0;
    int x0c = max(x0, 0), x1c = min(x0 + 1, TGD - 1);
    const bf16* hg = g_hglob + (size_t)bc * A3;
    float v00 = __bfloat162float(hg[y0c * TGD + x0c]), v01 = __bfloat162float(hg[y0c * TGD + x1c]);
    float v10 = __bfloat162float(hg[y1c * TGD + x0c]), v11 = __bfloat162float(hg[y1c * TGD + x1c]);
    float bil = (1.f - fy) * ((1.f - fx) * v00 + fx * v01) +
                fy * ((1.f - fx) * v10 + fx * v11);
    g_h[idx] = __float2bfloat16(0.75f * __bfloat162float(g_hpatch[idx]) + 0.25f * bil);
}

// ---------------- 11) proj + residual: A=wp m-major, B=h k-major ----------------
__global__ void k_proj(const float* __restrict__ x, float* __restrict__ out) {
    const int b = blockIdx.z;
    const int m0 = blockIdx.y * 128;
    const int n0 = blockIdx.x * 128;
    const bf16* hb = g_h + (size_t)b * CHW;
    const bf16* Wp = g_wb + 3 * CC * CC;

    __shared__ bf16 sA[2][128 * MS];
    __shared__ bf16 sB[2][32 * KS];
    const int tid = threadIdx.x, warp = tid >> 5, lane = tid & 31;
    float acc[2][8][4] = {};

    auto load = [&](int s, int kc) {
        int k0 = kc * 32;
#pragma unroll
        for (int i = 0; i < 2; i++) {
            int idx = tid + i * 256;
            int r = idx >> 2, seg = idx & 3;
            cp16(sptr(&sA[s][r * MS + seg * 8]), Wp + (m0 + r) * CC + k0 + seg * 8, true);
        }
#pragma unroll
        for (int i = 0; i < 2; i++) {
            int idx = tid + i * 256;
            int r = idx >> 4, seg = idx & 15;
            cp16(sptr(&sB[s][r * KS + seg * 8]), hb + (size_t)(k0 + r) * HWP + n0 + seg * 8, true);
        }
    };

    const int NK = 8;
    load(0, 0); cp_commit();
    for (int kc = 0; kc < NK; kc++) {
        if (kc + 1 < NK) load((kc + 1) & 1, kc + 1);
        cp_commit();
        cp_wait<1>();
        __syncthreads();
        tile_mma16<false, true>(sA[kc & 1], sB[kc & 1], acc, warp, lane);
        __syncthreads();
    }

    const int gr = lane >> 2, tg = lane & 3;
    const int m0w = 32 * (warp >> 1), n0w = 64 * (warp & 1);
#pragma unroll
    for (int mt = 0; mt < 2; mt++) {
        int mA = m0 + m0w + mt * 16 + gr;
#pragma unroll
        for (int nt = 0; nt < 8; nt++) {
            int n = n0 + n0w + nt * 8 + 2 * tg;
            size_t o0 = (size_t)b * CHW + (size_t)mA * HWP + n;
            size_t o1 = (size_t)b * CHW + (size_t)(mA + 8) * HWP + n;
            float2 x0 = *(const float2*)&x[o0];
            float2 x1 = *(const float2*)&x[o1];
            *(float2*)&out[o0] = make_float2(x0.x + acc[mt][nt][0], x0.y + acc[mt][nt][1]);
            *(float2*)&out[o1] = make_float2(x1.x + acc[mt][nt][2], x1.y + acc[mt][nt][3]);
        }
    }
}

// ---------------- launch ----------------
extern "C" void kernel_launch(void* const* d_in, const int* in_sizes, int n_in,
                              void* d_out, int out_size) {
    const float* x   = (const float*)d_in[0];
    const float* gnw = (const float*)d_in[1];
    const float* gnb = (const float*)d_in[2];
    const float* wq  = (const float*)d_in[3];
    const float* bq  = (const float*)d_in[4];
    const float* wk  = (const float*)d_in[5];
    const float* bk  = (const float*)d_in[6];
    const float* wv  = (const float*)d_in[7];
    const float* bv  = (const float*)d_in[8];
    const float* wp  = (const float*)d_in[9];
    float* out = (float*)d_out;

    k_wprep<<<(4 * CC * CC + 255) / 256, 256>>>(wq, wk, wv, wp);
    k_gn_stats<<<dim3(64, 8), 256>>>(x);
    k_gn_reduce<<<8, 64>>>();
    k_xn<<<(BB * CHW / 4 + 255) / 256, 256>>>(x, gnw, gnb);
    k_qkv<<<dim3(98, 6, 8), 256>>>(bq, bk, bv);
    k_pool<<<(BB * CC * A3 + 255) / 256, 256>>>();
    k_patt<<<dim3(2, 2, 128), 256>>>();
    k_psm<<<BB * PP, 256>>>();
    k_hpatch<<<dim3(2, 128, 8), 256>>>();
    k_gatt<<<dim3(25, 25, 8), 256>>>();
    k_gsm<<<BB * A3, 256>>>();
    k_hglob<<<dim3(25, 2, 8), 256>>>();
    k_comb<<<(BB * CHW + 255) / 256, 256>>>();
    k_proj<<<dim3(98, 2, 8), 256>>>(x, out);
}

// round 8
// speedup vs baseline: 5.9100x; 1.0116x over previous
#include <cuda_runtime.h>
#include <cuda_bf16.h>
#include <math.h>

typedef __nv_bfloat16 bf16;

// ---------------- problem constants ----------------
#define BB   8
#define CC   256
#define HH   112
#define WW   112
#define HWP  12544
#define CHW  3211264
#define PP   196
#define A3   3136
#define TGD  56

#define KS   136                // k-major smem stride (bf16 elems), [32][136]
#define MS   40                 // m/n-major smem stride (bf16 elems), [128][40]
#define APR  224                // attp padded row stride (zeros beyond 195)

// flash-global smem strides (bf16 elems)
#define FQS  72
#define FKS  136
#define FPS  136
#define FVS  136
#define SMEM_FG  143360         // bytes: Q(36864)+K(17408)+P(17408)+V(69632)+stats(2048)

// ---------------- scratch ----------------
__device__ bf16  g_xn[BB * CHW + 64];
__device__ bf16  g_q[BB * CHW + 64];
__device__ bf16  g_k[BB * CHW + 64];
__device__ bf16  g_v[BB * CHW + 64];
__device__ bf16  g_qp[BB * CC * A3 + 64];
__device__ bf16  g_kp[BB * CC * A3 + 64];
__device__ bf16  g_vp[BB * CC * A3 + 64];
__device__ float g_attp_part[16 * BB * PP * PP];
__device__ bf16  g_attp[BB * 256 * APR];            // zero-init pads
__device__ bf16  g_hpatch[BB * CHW + 64];
__device__ bf16  g_hglob[BB * CC * A3 + 64];
__device__ bf16  g_h[BB * CHW + 64];
__device__ bf16  g_wb[4 * CC * CC];
__device__ float g_spart[BB * 64 * 2];
__device__ float g_stats[BB * 2];

// ---------------- primitives ----------------
__device__ __forceinline__ unsigned sptr(const void* p) {
    return (unsigned)__cvta_generic_to_shared(p);
}
__device__ __forceinline__ void cp16(unsigned dst, const void* src, bool v) {
    asm volatile("cp.async.cg.shared.global [%0], [%1], 16, %2;"
                 :: "r"(dst), "l"(src), "r"(v ? 16 : 0));
}
__device__ __forceinline__ void cp8(unsigned dst, const void* src) {
    asm volatile("cp.async.ca.shared.global [%0], [%1], 8;" :: "r"(dst), "l"(src));
}
__device__ __forceinline__ void cp_commit() { asm volatile("cp.async.commit_group;"); }
template <int N>
__device__ __forceinline__ void cp_wait() { asm volatile("cp.async.wait_group %0;" :: "n"(N)); }

__device__ __forceinline__ void ldsm4(unsigned* r, unsigned addr) {
    asm volatile("ldmatrix.sync.aligned.m8n8.x4.shared.b16 {%0,%1,%2,%3}, [%4];"
                 : "=r"(r[0]), "=r"(r[1]), "=r"(r[2]), "=r"(r[3]) : "r"(addr));
}
__device__ __forceinline__ void ldsm4t(unsigned* r, unsigned addr) {
    asm volatile("ldmatrix.sync.aligned.m8n8.x4.trans.shared.b16 {%0,%1,%2,%3}, [%4];"
                 : "=r"(r[0]), "=r"(r[1]), "=r"(r[2]), "=r"(r[3]) : "r"(addr));
}
__device__ __forceinline__ void mma16(float* c, const unsigned* a, unsigned b0, unsigned b1) {
    asm volatile(
        "mma.sync.aligned.m16n8k16.row.col.f32.bf16.bf16.f32 "
        "{%0,%1,%2,%3}, {%4,%5,%6,%7}, {%8,%9}, {%0,%1,%2,%3};"
        : "+f"(c[0]), "+f"(c[1]), "+f"(c[2]), "+f"(c[3])
        : "r"(a[0]), "r"(a[1]), "r"(a[2]), "r"(a[3]), "r"(b0), "r"(b1));
}
__device__ __forceinline__ unsigned packbf(float x, float y) {
    __nv_bfloat162 t = __floats2bfloat162_rn(x, y);
    return *(unsigned*)&t;
}

// 128x128 block tile, 8 warps (warp w -> m-slab 32*(w>>1), n-slab 64*(w&1)), k-chunk 32.
template <bool AT, bool BT>
__device__ __forceinline__ void tile_mma16(const bf16* As, const bf16* Bs,
                                           float (&acc)[2][8][4], int warp, int lane) {
    const int m0w = 32 * (warp >> 1), n0w = 64 * (warp & 1);
    const int j = lane >> 3, i = lane & 7;
#pragma unroll
    for (int kt = 0; kt < 2; kt++) {
        const int k0 = kt * 16;
        unsigned a[2][4];
#pragma unroll
        for (int mt = 0; mt < 2; mt++) {
            if (AT) {
                const bf16* p = As + (size_t)(k0 + (j >> 1) * 8 + i) * KS
                              + m0w + mt * 16 + (j & 1) * 8;
                ldsm4t(a[mt], sptr(p));
            } else {
                const bf16* p = As + (size_t)(m0w + mt * 16 + (j & 1) * 8 + i) * MS
                              + k0 + (j >> 1) * 8;
                ldsm4(a[mt], sptr(p));
            }
        }
#pragma unroll
        for (int ng = 0; ng < 4; ng++) {
            unsigned b[4];
            if (BT) {
                const bf16* p = Bs + (size_t)(k0 + (j & 1) * 8 + i) * KS
                              + n0w + ng * 16 + (j >> 1) * 8;
                ldsm4t(b, sptr(p));
            } else {
                const bf16* p = Bs + (size_t)(n0w + ng * 16 + (j >> 1) * 8 + i) * MS
                              + k0 + (j & 1) * 8;
                ldsm4(b, sptr(p));
            }
            mma16(acc[0][ng * 2],     a[0], b[0], b[1]);
            mma16(acc[0][ng * 2 + 1], a[0], b[2], b[3]);
            mma16(acc[1][ng * 2],     a[1], b[0], b[1]);
            mma16(acc[1][ng * 2 + 1], a[1], b[2], b[3]);
        }
    }
}

// ---------------- 0) weights -> bf16 ----------------
__global__ void k_wprep(const float* __restrict__ wq, const float* __restrict__ wk,
                        const float* __restrict__ wv, const float* __restrict__ wp) {
    int idx = blockIdx.x * blockDim.x + threadIdx.x;
    if (idx >= 4 * CC * CC) return;
    int w = idx >> 16, r = idx & 65535;
    const float* src = (w == 0) ? wq : (w == 1) ? wk : (w == 2) ? wv : wp;
    g_wb[idx] = __float2bfloat16(src[r]);
}

// ---------------- 1) GroupNorm stats ----------------
__global__ void k_gn_stats(const float* __restrict__ x) {
    int b = blockIdx.y;
    const float* xb = x + (size_t)b * CHW;
    float s1 = 0.f, s2 = 0.f;
    for (int i = blockIdx.x * blockDim.x + threadIdx.x; i < CHW;
         i += gridDim.x * blockDim.x) {
        float v = xb[i];
        s1 += v; s2 += v * v;
    }
    __shared__ float sm1[256], sm2[256];
    int t = threadIdx.x;
    sm1[t] = s1; sm2[t] = s2;
    __syncthreads();
    for (int o = 128; o > 0; o >>= 1) {
        if (t < o) { sm1[t] += sm1[t + o]; sm2[t] += sm2[t + o]; }
        __syncthreads();
    }
    if (t == 0) {
        g_spart[(b * 64 + blockIdx.x) * 2 + 0] = sm1[0];
        g_spart[(b * 64 + blockIdx.x) * 2 + 1] = sm2[0];
    }
}

__global__ void k_gn_reduce() {
    int b = blockIdx.x, t = threadIdx.x;
    __shared__ float sm1[64], sm2[64];
    sm1[t] = g_spart[(b * 64 + t) * 2 + 0];
    sm2[t] = g_spart[(b * 64 + t) * 2 + 1];
    __syncthreads();
    for (int o = 32; o > 0; o >>= 1) {
        if (t < o) { sm1[t] += sm1[t + o]; sm2[t] += sm2[t + o]; }
        __syncthreads();
    }
    if (t == 0) {
        g_stats[b * 2 + 0] = sm1[0];
        g_stats[b * 2 + 1] = sm2[0];
    }
}

// ---------------- 1b) apply GN -> bf16 ----------------
__global__ void k_xn(const float* __restrict__ x,
                     const float* __restrict__ gnw, const float* __restrict__ gnb) {
    int idx = blockIdx.x * blockDim.x + threadIdx.x;
    if (idx >= BB * CHW / 4) return;
    int fi = idx * 4;
    int b = fi / CHW;
    int rem = fi - b * CHW;
    int c = rem / HWP;
    float s1 = g_stats[b * 2], s2 = g_stats[b * 2 + 1];
    const float invN = 1.0f / (float)CHW;
    float mu = s1 * invN;
    float rstd = rsqrtf(s2 * invN - mu * mu + 1e-5f);
    float sc = rstd * gnw[c];
    float sh = gnb[c] - mu * sc;
    float4 v = *(const float4*)&x[fi];
    bf16* o = &g_xn[fi];
    *(__nv_bfloat162*)o       = __floats2bfloat162_rn(v.x * sc + sh, v.y * sc + sh);
    *(__nv_bfloat162*)(o + 2) = __floats2bfloat162_rn(v.z * sc + sh, v.w * sc + sh);
}

// ---------------- 2) QKV: A=W bf16 m-major, B=xn bf16 k-major ----------------
__global__ void k_qkv(const float* __restrict__ bq, const float* __restrict__ bk,
                      const float* __restrict__ bv) {
    const int b = blockIdx.z;
    const int n0 = blockIdx.x * 128;
    const int m0g = blockIdx.y * 128;
    const int sel = m0g >> 8;
    const int m0 = m0g & 255;
    const bf16* Wsel = g_wb + sel * CC * CC;
    const float* Bias = (sel == 0) ? bq : (sel == 1) ? bk : bv;
    bf16* Out         = (sel == 0) ? g_q : (sel == 1) ? g_k : g_v;
    const bf16* xnb = g_xn + (size_t)b * CHW;

    __shared__ bf16 sA[2][128 * MS];
    __shared__ bf16 sB[2][32 * KS];
    const int tid = threadIdx.x, warp = tid >> 5, lane = tid & 31;
    float acc[2][8][4] = {};

    auto load = [&](int s, int kc) {
        int k0 = kc * 32;
#pragma unroll
        for (int i = 0; i < 2; i++) {
            int idx = tid + i * 256;
            int r = idx >> 2, seg = idx & 3;
            cp16(sptr(&sA[s][r * MS + seg * 8]), Wsel + (m0 + r) * CC + k0 + seg * 8, true);
        }
#pragma unroll
        for (int i = 0; i < 2; i++) {
            int idx = tid + i * 256;
            int r = idx >> 4, seg = idx & 15;
            cp16(sptr(&sB[s][r * KS + seg * 8]), xnb + (size_t)(k0 + r) * HWP + n0 + seg * 8, true);
        }
    };

    const int NK = 8;
    load(0, 0); cp_commit();
    for (int kc = 0; kc < NK; kc++) {
        if (kc + 1 < NK) load((kc + 1) & 1, kc + 1);
        cp_commit();
        cp_wait<1>();
        __syncthreads();
        tile_mma16<false, true>(sA[kc & 1], sB[kc & 1], acc, warp, lane);
        __syncthreads();
    }

    const int gr = lane >> 2, tg = lane & 3;
    const int m0w = 32 * (warp >> 1), n0w = 64 * (warp & 1);
#pragma unroll
    for (int mt = 0; mt < 2; mt++) {
        int mA = m0 + m0w + mt * 16 + gr;
        float bA = Bias[mA], bB = Bias[mA + 8];
#pragma unroll
        for (int nt = 0; nt < 8; nt++) {
            int n = n0 + n0w + nt * 8 + 2 * tg;
            *(unsigned*)&Out[(size_t)(b * CC + mA) * HWP + n] =
                packbf(acc[mt][nt][0] + bA, acc[mt][nt][1] + bA);
            *(unsigned*)&Out[(size_t)(b * CC + mA + 8) * HWP + n] =
                packbf(acc[mt][nt][2] + bB, acc[mt][nt][3] + bB);
        }
    }
}

// ---------------- 3) 2x2 average pool ----------------
__global__ void k_pool() {
    int idx = blockIdx.x * blockDim.x + threadIdx.x;
    if (idx >= BB * CC * A3) return;
    int t = idx % A3;
    int bc = idx / A3;
    int ty = t / TGD, tx = t % TGD;
    size_t base = (size_t)bc * HWP + (size_t)(2 * ty) * WW + 2 * tx;
    g_qp[idx] = __float2bfloat16(0.25f * (__bfloat162float(g_q[base]) + __bfloat162float(g_q[base + 1]) +
                                          __bfloat162float(g_q[base + WW]) + __bfloat162float(g_q[base + WW + 1])));
    g_kp[idx] = __float2bfloat16(0.25f * (__bfloat162float(g_k[base]) + __bfloat162float(g_k[base + 1]) +
                                          __bfloat162float(g_k[base + WW]) + __bfloat162float(g_k[base + WW + 1])));
    g_vp[idx] = __float2bfloat16(0.25f * (__bfloat162float(g_v[base]) + __bfloat162float(g_v[base + 1]) +
                                          __bfloat162float(g_v[base + WW]) + __bfloat162float(g_v[base + WW + 1])));
}

// ---------------- 4) patch logits: A=q, B=k, both k-major; split-K=16 ----------------
__global__ void k_patt() {
    const int bz = blockIdx.z;
    const int b = bz >> 4, ks = bz & 15;
    const int m0 = blockIdx.y * 128, n0 = blockIdx.x * 128;
    const bf16* qb = g_q + (size_t)b * CHW;
    const bf16* kb = g_k + (size_t)b * CHW;

    __shared__ bf16 sA[2][32 * KS];
    __shared__ bf16 sB[2][32 * KS];
    const int tid = threadIdx.x, warp = tid >> 5, lane = tid & 31;
    float acc[2][8][4] = {};

    auto load = [&](int s, int kc) {
        int k0 = ks * 1024 + kc * 32;
#pragma unroll
        for (int i = 0; i < 4; i++) {
            int idx = tid + i * 256;
            int tile = idx >> 9, rem = idx & 511;
            int r = rem >> 4, seg = rem & 15;
            int base0 = tile ? n0 : m0;
            const bf16* gsrc = tile ? kb : qb;
            bf16* st = tile ? &sB[s][0] : &sA[s][0];
            int gm = base0 + seg * 8;
            unsigned dst = sptr(st + r * KS + seg * 8);
            const bf16* sp = gsrc + (size_t)(k0 + r) * PP + gm;
            if (gm + 8 <= PP) {
                cp8(dst, sp);
                cp8(dst + 8, sp + 4);
            } else if (gm < PP) {
                cp8(dst, sp);
            } else {
                cp16(dst, gsrc, false);
            }
        }
    };

    const int NK = 32;
    load(0, 0); cp_commit();
    for (int kc = 0; kc < NK; kc++) {
        if (kc + 1 < NK) load((kc + 1) & 1, kc + 1);
        cp_commit();
        cp_wait<1>();
        __syncthreads();
        tile_mma16<true, true>(sA[kc & 1], sB[kc & 1], acc, warp, lane);
        __syncthreads();
    }

    const float scale = 1.0f / 128.0f;
    const int gr = lane >> 2, tg = lane & 3;
    const int m0w = 32 * (warp >> 1), n0w = 64 * (warp & 1);
    float* ob = g_attp_part + (size_t)(ks * BB + b) * PP * PP;
#pragma unroll
    for (int mt = 0; mt < 2; mt++) {
#pragma unroll
        for (int nt = 0; nt < 8; nt++) {
            int n = n0 + n0w + nt * 8 + 2 * tg;
            if (n >= PP) continue;
            int mA = m0 + m0w + mt * 16 + gr;
            if (mA < PP)
                *(float2*)&ob[(size_t)mA * PP + n] =
                    make_float2(acc[mt][nt][0] * scale, acc[mt][nt][1] * scale);
            if (mA + 8 < PP)
                *(float2*)&ob[(size_t)(mA + 8) * PP + n] =
                    make_float2(acc[mt][nt][2] * scale, acc[mt][nt][3] * scale);
        }
    }
}

// ---------------- 5) patch softmax -> bf16 padded attp ----------------
__global__ void k_psm() {
    int row = blockIdx.x;
    int b = row / PP, p = row % PP;
    __shared__ float srow[PP];
    __shared__ float red[256];
    int t = threadIdx.x;
    for (int q = t; q < PP; q += 256) {
        float s = 0.f;
#pragma unroll
        for (int ks = 0; ks < 16; ks++)
            s += g_attp_part[(size_t)ks * (BB * PP * PP) + (size_t)row * PP + q];
        srow[q] = s;
    }
    __syncthreads();
    float mx = -1e30f;
    for (int q = t; q < PP; q += 256) mx = fmaxf(mx, srow[q]);
    red[t] = mx;
    __syncthreads();
    for (int o = 128; o > 0; o >>= 1) { if (t < o) red[t] = fmaxf(red[t], red[t + o]); __syncthreads(); }
    mx = red[0];
    __syncthreads();
    float s = 0.f;
    for (int q = t; q < PP; q += 256) { float e = __expf(srow[q] - mx); srow[q] = e; s += e; }
    red[t] = s;
    __syncthreads();
    for (int o = 128; o > 0; o >>= 1) { if (t < o) red[t] += red[t + o]; __syncthreads(); }
    float inv = 1.0f / red[0];
    bf16* ob = g_attp + ((size_t)b * 256 + p) * APR;
    for (int q = t; q < PP; q += 256) ob[q] = __float2bfloat16(srow[q] * inv);
}

// ---------------- 6) h_patch = V @ att^T ----------------
__global__ void k_hpatch() {
    const int b = blockIdx.z;
    const int m0 = blockIdx.y * 128;
    const int n0 = blockIdx.x * 128;
    const bf16* vb = g_v + (size_t)b * CHW;
    const bf16* apb = g_attp + (size_t)b * 256 * APR;

    __shared__ bf16 sA[2][128 * MS];
    __shared__ bf16 sB[2][128 * MS];
    const int tid = threadIdx.x, warp = tid >> 5, lane = tid & 31;
    float acc[2][8][4] = {};

    auto load = [&](int s, int kc) {
        int k0 = kc * 32;
#pragma unroll
        for (int i = 0; i < 4; i++) {
            int idx = tid + i * 256;
            int tile = idx >> 9, rem = idx & 511;
            int r = rem >> 2, seg = rem & 3;
            if (tile == 0) {
                unsigned dst = sptr(&sA[s][r * MS + seg * 8]);
                const bf16* sp = vb + (size_t)(m0 + r) * PP + k0 + seg * 8;
                cp8(dst, sp);
                cp8(dst + 8, sp + 4);
            } else {
                cp16(sptr(&sB[s][r * MS + seg * 8]),
                     apb + (size_t)(n0 + r) * APR + k0 + seg * 8, true);
            }
        }
    };

    const int NK = 7;
    load(0, 0); cp_commit();
    for (int kc = 0; kc < NK; kc++) {
        if (kc + 1 < NK) load((kc + 1) & 1, kc + 1);
        cp_commit();
        cp_wait<1>();
        __syncthreads();
        tile_mma16<false, false>(sA[kc & 1], sB[kc & 1], acc, warp, lane);
        __syncthreads();
    }

    const int gr = lane >> 2, tg = lane & 3;
    const int m0w = 32 * (warp >> 1), n0w = 64 * (warp & 1);
    bf16* ob = g_hpatch + (size_t)b * CHW;
#pragma unroll
    for (int mt = 0; mt < 2; mt++) {
        int mA = m0 + m0w + mt * 16 + gr;
#pragma unroll
        for (int nt = 0; nt < 8; nt++) {
            int n = n0 + n0w + nt * 8 + 2 * tg;
            if (n >= PP) continue;
            *(unsigned*)&ob[(size_t)mA * PP + n] = packbf(acc[mt][nt][0], acc[mt][nt][1]);
            *(unsigned*)&ob[(size_t)(mA + 8) * PP + n] = packbf(acc[mt][nt][2], acc[mt][nt][3]);
        }
    }
}

// ---------------- 7) flash global attention: replaces gatt+gsm+hglob ----------------
// 512 threads / 16 warps. Q tile 64 pos x 256 ch resident; kv chunks of 128.
// S phase: warp w -> m-slab 16*(w>>2), n-slab 32*(w&3).  PV: d-slab 64*(w&3).
__global__ void k_fglob() {
    extern __shared__ bf16 fsm[];
    bf16* sQ = fsm;                       // [256][FQS]
    bf16* sK = sQ + 256 * FQS;            // [2][32][FKS]
    bf16* sP = sK + 2 * 32 * FKS;         // [64][FPS]
    bf16* sV = sP + 64 * FPS;             // [256][FVS]
    float* sMax = (float*)(sV + 256 * FVS);   // [4][64]
    float* sSum = sMax + 256;                 // [4][64]

    const int b = blockIdx.y;
    const int q0 = blockIdx.x * 64;
    const bf16* qp = g_qp + (size_t)b * CC * A3;
    const bf16* kp = g_kp + (size_t)b * CC * A3;
    const bf16* vp = g_vp + (size_t)b * CC * A3;

    const int tid = threadIdx.x, warp = tid >> 5, lane = tid & 31;
    const int mw = 16 * (warp >> 2);
    const int nw = 32 * (warp & 3);
    const int dw = 64 * (warp & 3);
    const int j = lane >> 3, i = lane & 7;
    const int gr = lane >> 2, tg = lane & 3;

    // Q tile load (2048 x cp16 over 512 threads)
#pragma unroll
    for (int it = 0; it < 4; it++) {
        int idx = tid + it * 512;
        int c = idx >> 3, seg = idx & 7;
        cp16(sptr(&sQ[c * FQS + seg * 8]), qp + (size_t)c * A3 + q0 + seg * 8, true);
    }
    cp_commit();

    float m_r[2] = {-1e30f, -1e30f}, l_r[2] = {0.f, 0.f};
    float acc_o[8][4] = {};

    const int NCH = 25;                  // ceil(3136/128); last chunk half-valid
    for (int ch = 0; ch < NCH; ch++) {
        const int kv0 = ch * 128;

        // ---- S = Q K^T over 8 c-chunks of 32, K double-buffered ----
        auto loadK = [&](int s, int cc) {
            int r = tid >> 4, seg = tid & 15;
            int q = kv0 + seg * 8;
            bool v = q < A3;
            cp16(sptr(&sK[s * 32 * FKS + r * FKS + seg * 8]),
                 kp + (size_t)(cc * 32 + r) * A3 + (v ? q : 0), v);
        };
        float acc_s[4][4] = {};
        loadK(0, 0); cp_commit();
#pragma unroll
        for (int cc = 0; cc < 8; cc++) {
            if (cc < 7) loadK((cc + 1) & 1, cc + 1);
            cp_commit();
            cp_wait<1>();
            __syncthreads();
            const bf16* Kb = &sK[(cc & 1) * 32 * FKS];
            const int cq = cc * 32;
#pragma unroll
            for (int kt = 0; kt < 2; kt++) {
                unsigned a[4];
                ldsm4t(a, sptr(&sQ[(cq + kt * 16 + (j >> 1) * 8 + i) * FQS + mw + (j & 1) * 8]));
#pragma unroll
                for (int ng = 0; ng < 2; ng++) {
                    unsigned bb[4];
                    ldsm4t(bb, sptr(&Kb[(kt * 16 + (j & 1) * 8 + i) * FKS + nw + ng * 16 + (j >> 1) * 8]));
                    mma16(acc_s[ng * 2],     a, bb[0], bb[1]);
                    mma16(acc_s[ng * 2 + 1], a, bb[2], bb[3]);
                }
            }
            __syncthreads();
        }

        // ---- prefetch V chunk (256 d x 128 q) while doing softmax ----
#pragma unroll
        for (int it = 0; it < 8; it++) {
            int idx = tid + it * 512;
            int d = idx >> 4, seg = idx & 15;
            int q = kv0 + seg * 8;
            bool v = q < A3;
            cp16(sptr(&sV[d * FVS + seg * 8]), vp + (size_t)d * A3 + (v ? q : 0), v);
        }
        cp_commit();

        // ---- online softmax ----
        float mx[2] = {-1e30f, -1e30f};
#pragma unroll
        for (int nt = 0; nt < 4; nt++) {
            int col = kv0 + nw + nt * 8 + 2 * tg;
#pragma unroll
            for (int e = 0; e < 4; e++) {
                float s = acc_s[nt][e] * 0.0625f;        // C^-0.5
                s = ((col + (e & 1)) < A3) ? s : -1e30f;
                acc_s[nt][e] = s;
                mx[e >> 1] = fmaxf(mx[e >> 1], s);
            }
        }
#pragma unroll
        for (int o = 1; o < 4; o <<= 1) {
            mx[0] = fmaxf(mx[0], __shfl_xor_sync(~0u, mx[0], o));
            mx[1] = fmaxf(mx[1], __shfl_xor_sync(~0u, mx[1], o));
        }
        if (tg == 0) {
            sMax[(warp & 3) * 64 + mw + gr]     = mx[0];
            sMax[(warp & 3) * 64 + mw + 8 + gr] = mx[1];
        }
        __syncthreads();
        float mnew[2], alpha[2];
#pragma unroll
        for (int h = 0; h < 2; h++) {
            int r = mw + h * 8 + gr;
            float cm = fmaxf(fmaxf(sMax[r], sMax[64 + r]), fmaxf(sMax[128 + r], sMax[192 + r]));
            mnew[h] = fmaxf(m_r[h], cm);
            alpha[h] = __expf(m_r[h] - mnew[h]);
            m_r[h] = mnew[h];
        }
        float sum[2] = {0.f, 0.f};
#pragma unroll
        for (int nt = 0; nt < 4; nt++) {
            int col = nw + nt * 8 + 2 * tg;
            float p0 = __expf(acc_s[nt][0] - mnew[0]);
            float p1 = __expf(acc_s[nt][1] - mnew[0]);
            float p2 = __expf(acc_s[nt][2] - mnew[1]);
            float p3 = __expf(acc_s[nt][3] - mnew[1]);
            sum[0] += p0 + p1;
            sum[1] += p2 + p3;
            *(unsigned*)&sP[(mw + gr) * FPS + col]     = packbf(p0, p1);
            *(unsigned*)&sP[(mw + 8 + gr) * FPS + col] = packbf(p2, p3);
        }
#pragma unroll
        for (int o = 1; o < 4; o <<= 1) {
            sum[0] += __shfl_xor_sync(~0u, sum[0], o);
            sum[1] += __shfl_xor_sync(~0u, sum[1], o);
        }
        if (tg == 0) {
            sSum[(warp & 3) * 64 + mw + gr]     = sum[0];
            sSum[(warp & 3) * 64 + mw + 8 + gr] = sum[1];
        }
        // rescale O accumulators
#pragma unroll
        for (int nt = 0; nt < 8; nt++) {
            acc_o[nt][0] *= alpha[0]; acc_o[nt][1] *= alpha[0];
            acc_o[nt][2] *= alpha[1]; acc_o[nt][3] *= alpha[1];
        }
        __syncthreads();
#pragma unroll
        for (int h = 0; h < 2; h++) {
            int r = mw + h * 8 + gr;
            l_r[h] = l_r[h] * alpha[h] + sSum[r] + sSum[64 + r] + sSum[128 + r] + sSum[192 + r];
        }
        cp_wait<0>();
        __syncthreads();

        // ---- O += P V : k=q (8 kt of 16), d-slab dw (4 groups of 16) ----
#pragma unroll
        for (int kt = 0; kt < 8; kt++) {
            unsigned a[4];
            ldsm4(a, sptr(&sP[(mw + (j & 1) * 8 + i) * FPS + kt * 16 + (j >> 1) * 8]));
#pragma unroll
            for (int ng = 0; ng < 4; ng++) {
                unsigned bb[4];
                ldsm4(bb, sptr(&sV[(dw + ng * 16 + (j >> 1) * 8 + i) * FVS + kt * 16 + (j & 1) * 8]));
                mma16(acc_o[ng * 2],     a, bb[0], bb[1]);
                mma16(acc_o[ng * 2 + 1], a, bb[2], bb[3]);
            }
        }
        __syncthreads();
    }

    // ---- epilogue: O /= l, write hglob[c][pos] ----
    bf16* ob = g_hglob + (size_t)b * CC * A3;
    float invl[2] = {1.f / l_r[0], 1.f / l_r[1]};
    int p0 = q0 + mw + gr, p1 = p0 + 8;
#pragma unroll
    for (int nt = 0; nt < 8; nt++) {
        int d = dw + (nt >> 1) * 16 + (nt & 1) * 8 + 2 * tg;
        ob[(size_t)d * A3 + p0]       = __float2bfloat16(acc_o[nt][0] * invl[0]);
        ob[(size_t)(d + 1) * A3 + p0] = __float2bfloat16(acc_o[nt][1] * invl[0]);
        ob[(size_t)d * A3 + p1]       = __float2bfloat16(acc_o[nt][2] * invl[1]);
        ob[(size_t)(d + 1) * A3 + p1] = __float2bfloat16(acc_o[nt][3] * invl[1]);
    }
}

// ---------------- 10) combine -> bf16 h ----------------
__global__ void k_comb() {
    int idx = blockIdx.x * blockDim.x + threadIdx.x;
    if (idx >= BB * CHW) return;
    int hw = idx % HWP;
    int bc = idx / HWP;
    int i = hw / WW, j = hw % WW;
    float sy = 0.5f * i - 0.25f;
    int y0 = (int)floorf(sy);
    float fy = sy - (float)y0;
    int y0c = max(y0, 0), y1c = min(y0 + 1, TGD - 1);
    float sx = 0.5f * j - 0.25f;
    int x0 = (int)floorf(sx);
    float fx = sx - (float)x0;
    int x0c = max(x0, 0), x1c = min(x0 + 1, TGD - 1);
    const bf16* hg = g_hglob + (size_t)bc * A3;
    float v00 = __bfloat162float(hg[y0c * TGD + x0c]), v01 = __bfloat162float(hg[y0c * TGD + x1c]);
    float v10 = __bfloat162float(hg[y1c * TGD + x0c]), v11 = __bfloat162float(hg[y1c * TGD + x1c]);
    float bil = (1.f - fy) * ((1.f - fx) * v00 + fx * v01) +
                fy * ((1.f - fx) * v10 + fx * v11);
    g_h[idx] = __float2bfloat16(0.75f * __bfloat162float(g_hpatch[idx]) + 0.25f * bil);
}

// ---------------- 11) proj + residual ----------------
__global__ void k_proj(const float* __restrict__ x, float* __restrict__ out) {
    const int b = blockIdx.z;
    const int m0 = blockIdx.y * 128;
    const int n0 = blockIdx.x * 128;
    const bf16* hb = g_h + (size_t)b * CHW;
    const bf16* Wp = g_wb + 3 * CC * CC;

    __shared__ bf16 sA[2][128 * MS];
    __shared__ bf16 sB[2][32 * KS];
    const int tid = threadIdx.x, warp = tid >> 5, lane = tid & 31;
    float acc[2][8][4] = {};

    auto load = [&](int s, int kc) {
        int k0 = kc * 32;
#pragma unroll
        for (int i = 0; i < 2; i++) {
            int idx = tid + i * 256;
            int r = idx >> 2, seg = idx & 3;
            cp16(sptr(&sA[s][r * MS + seg * 8]), Wp + (m0 + r) * CC + k0 + seg * 8, true);
        }
#pragma unroll
        for (int i = 0; i < 2; i++) {
            int idx = tid + i * 256;
            int r = idx >> 4, seg = idx & 15;
            cp16(sptr(&sB[s][r * KS + seg * 8]), hb + (size_t)(k0 + r) * HWP + n0 + seg * 8, true);
        }
    };

    const int NK = 8;
    load(0, 0); cp_commit();
    for (int kc = 0; kc < NK; kc++) {
        if (kc + 1 < NK) load((kc + 1) & 1, kc + 1);
        cp_commit();
        cp_wait<1>();
        __syncthreads();
        tile_mma16<false, true>(sA[kc & 1], sB[kc & 1], acc, warp, lane);
        __syncthreads();
    }

    const int gr = lane >> 2, tg = lane & 3;
    const int m0w = 32 * (warp >> 1), n0w = 64 * (warp & 1);
#pragma unroll
    for (int mt = 0; mt < 2; mt++) {
        int mA = m0 + m0w + mt * 16 + gr;
#pragma unroll
        for (int nt = 0; nt < 8; nt++) {
            int n = n0 + n0w + nt * 8 + 2 * tg;
            size_t o0 = (size_t)b * CHW + (size_t)mA * HWP + n;
            size_t o1 = (size_t)b * CHW + (size_t)(mA + 8) * HWP + n;
            float2 x0 = *(const float2*)&x[o0];
            float2 x1 = *(const float2*)&x[o1];
            *(float2*)&out[o0] = make_float2(x0.x + acc[mt][nt][0], x0.y + acc[mt][nt][1]);
            *(float2*)&out[o1] = make_float2(x1.x + acc[mt][nt][2], x1.y + acc[mt][nt][3]);
        }
    }
}

// ---------------- launch ----------------
extern "C" void kernel_launch(void* const* d_in, const int* in_sizes, int n_in,
                              void* d_out, int out_size) {
    const float* x   = (const float*)d_in[0];
    const float* gnw = (const float*)d_in[1];
    const float* gnb = (const float*)d_in[2];
    const float* wq  = (const float*)d_in[3];
    const float* bq  = (const float*)d_in[4];
    const float* wk  = (const float*)d_in[5];
    const float* bk  = (const float*)d_in[6];
    const float* wv  = (const float*)d_in[7];
    const float* bv  = (const float*)d_in[8];
    const float* wp  = (const float*)d_in[9];
    float* out = (float*)d_out;

    static bool attr_set = false;
    if (!attr_set) {
        cudaFuncSetAttribute(k_fglob, cudaFuncAttributeMaxDynamicSharedMemorySize, SMEM_FG);
        attr_set = true;
    }

    k_wprep<<<(4 * CC * CC + 255) / 256, 256>>>(wq, wk, wv, wp);
    k_gn_stats<<<dim3(64, 8), 256>>>(x);
    k_gn_reduce<<<8, 64>>>();
    k_xn<<<(BB * CHW / 4 + 255) / 256, 256>>>(x, gnw, gnb);
    k_qkv<<<dim3(98, 6, 8), 256>>>(bq, bk, bv);
    k_pool<<<(BB * CC * A3 + 255) / 256, 256>>>();
    k_patt<<<dim3(2, 2, 128), 256>>>();
    k_psm<<<BB * PP, 256>>>();
    k_hpatch<<<dim3(2, 128, 8), 256>>>();
    k_fglob<<<dim3(49, 8), 512, SMEM_FG>>>();
    k_comb<<<(BB * CHW + 255) / 256, 256>>>();
    k_proj<<<dim3(98, 2, 8), 256>>>(x, out);
}

// round 9
// speedup vs baseline: 6.5266x; 1.1043x over previous
#include <cuda_runtime.h>
#include <cuda_bf16.h>
#include <math.h>

typedef __nv_bfloat16 bf16;

// ---------------- problem constants ----------------
#define BB   8
#define CC   256
#define HH   112
#define WW   112
#define HWP  12544
#define CHW  3211264
#define PP   196
#define A3   3136
#define TGD  56

#define KS   136                // k-major smem stride (bf16 elems), [32][136]
#define MS   40                 // m/n-major smem stride (bf16 elems), [128][40]
#define APR  224                // attp padded row stride (zeros beyond 195)

// flash-global smem strides (bf16 elems)
#define FQS  72
#define FKS  136
#define FPS  136
#define FVS  136
// bytes: Q(36864) + K(69632) + P(17408) + V(69632) + stats(2048)
#define SMEM_FG  195584

// ---------------- scratch ----------------
__device__ bf16  g_xn[BB * CHW + 64];
__device__ bf16  g_q[BB * CHW + 64];
__device__ bf16  g_k[BB * CHW + 64];
__device__ bf16  g_v[BB * CHW + 64];
__device__ bf16  g_qp[BB * CC * A3 + 64];
__device__ bf16  g_kp[BB * CC * A3 + 64];
__device__ bf16  g_vp[BB * CC * A3 + 64];
__device__ float g_attp_part[16 * BB * PP * PP];
__device__ bf16  g_attp[BB * 256 * APR];            // zero-init pads
__device__ bf16  g_hpatch[BB * CHW + 64];
__device__ bf16  g_hglob[BB * CC * A3 + 64];
__device__ bf16  g_h[BB * CHW + 64];
__device__ bf16  g_wb[4 * CC * CC];
__device__ float g_spart[BB * 64 * 2];
__device__ float g_stats[BB * 2];

// ---------------- primitives ----------------
__device__ __forceinline__ unsigned sptr(const void* p) {
    return (unsigned)__cvta_generic_to_shared(p);
}
__device__ __forceinline__ void cp16(unsigned dst, const void* src, bool v) {
    asm volatile("cp.async.cg.shared.global [%0], [%1], 16, %2;"
                 :: "r"(dst), "l"(src), "r"(v ? 16 : 0));
}
__device__ __forceinline__ void cp8(unsigned dst, const void* src) {
    asm volatile("cp.async.ca.shared.global [%0], [%1], 8;" :: "r"(dst), "l"(src));
}
__device__ __forceinline__ void cp_commit() { asm volatile("cp.async.commit_group;"); }
template <int N>
__device__ __forceinline__ void cp_wait() { asm volatile("cp.async.wait_group %0;" :: "n"(N)); }

__device__ __forceinline__ void ldsm4(unsigned* r, unsigned addr) {
    asm volatile("ldmatrix.sync.aligned.m8n8.x4.shared.b16 {%0,%1,%2,%3}, [%4];"
                 : "=r"(r[0]), "=r"(r[1]), "=r"(r[2]), "=r"(r[3]) : "r"(addr));
}
__device__ __forceinline__ void ldsm4t(unsigned* r, unsigned addr) {
    asm volatile("ldmatrix.sync.aligned.m8n8.x4.trans.shared.b16 {%0,%1,%2,%3}, [%4];"
                 : "=r"(r[0]), "=r"(r[1]), "=r"(r[2]), "=r"(r[3]) : "r"(addr));
}
__device__ __forceinline__ void mma16(float* c, const unsigned* a, unsigned b0, unsigned b1) {
    asm volatile(
        "mma.sync.aligned.m16n8k16.row.col.f32.bf16.bf16.f32 "
        "{%0,%1,%2,%3}, {%4,%5,%6,%7}, {%8,%9}, {%0,%1,%2,%3};"
        : "+f"(c[0]), "+f"(c[1]), "+f"(c[2]), "+f"(c[3])
        : "r"(a[0]), "r"(a[1]), "r"(a[2]), "r"(a[3]), "r"(b0), "r"(b1));
}
__device__ __forceinline__ unsigned packbf(float x, float y) {
    __nv_bfloat162 t = __floats2bfloat162_rn(x, y);
    return *(unsigned*)&t;
}

// 128x128 block tile, 8 warps (warp w -> m-slab 32*(w>>1), n-slab 64*(w&1)), k-chunk 32.
template <bool AT, bool BT>
__device__ __forceinline__ void tile_mma16(const bf16* As, const bf16* Bs,
                                           float (&acc)[2][8][4], int warp, int lane) {
    const int m0w = 32 * (warp >> 1), n0w = 64 * (warp & 1);
    const int j = lane >> 3, i = lane & 7;
#pragma unroll
    for (int kt = 0; kt < 2; kt++) {
        const int k0 = kt * 16;
        unsigned a[2][4];
#pragma unroll
        for (int mt = 0; mt < 2; mt++) {
            if (AT) {
                const bf16* p = As + (size_t)(k0 + (j >> 1) * 8 + i) * KS
                              + m0w + mt * 16 + (j & 1) * 8;
                ldsm4t(a[mt], sptr(p));
            } else {
                const bf16* p = As + (size_t)(m0w + mt * 16 + (j & 1) * 8 + i) * MS
                              + k0 + (j >> 1) * 8;
                ldsm4(a[mt], sptr(p));
            }
        }
#pragma unroll
        for (int ng = 0; ng < 4; ng++) {
            unsigned b[4];
            if (BT) {
                const bf16* p = Bs + (size_t)(k0 + (j & 1) * 8 + i) * KS
                              + n0w + ng * 16 + (j >> 1) * 8;
                ldsm4t(b, sptr(p));
            } else {
                const bf16* p = Bs + (size_t)(n0w + ng * 16 + (j >> 1) * 8 + i) * MS
                              + k0 + (j & 1) * 8;
                ldsm4(b, sptr(p));
            }
            mma16(acc[0][ng * 2],     a[0], b[0], b[1]);
            mma16(acc[0][ng * 2 + 1], a[0], b[2], b[3]);
            mma16(acc[1][ng * 2],     a[1], b[0], b[1]);
            mma16(acc[1][ng * 2 + 1], a[1], b[2], b[3]);
        }
    }
}

// ---------------- 0) weights -> bf16 ----------------
__global__ void k_wprep(const float* __restrict__ wq, const float* __restrict__ wk,
                        const float* __restrict__ wv, const float* __restrict__ wp) {
    int idx = blockIdx.x * blockDim.x + threadIdx.x;
    if (idx >= 4 * CC * CC) return;
    int w = idx >> 16, r = idx & 65535;
    const float* src = (w == 0) ? wq : (w == 1) ? wk : (w == 2) ? wv : wp;
    g_wb[idx] = __float2bfloat16(src[r]);
}

// ---------------- 1) GroupNorm stats ----------------
__global__ void k_gn_stats(const float* __restrict__ x) {
    int b = blockIdx.y;
    const float* xb = x + (size_t)b * CHW;
    float s1 = 0.f, s2 = 0.f;
    for (int i = blockIdx.x * blockDim.x + threadIdx.x; i < CHW;
         i += gridDim.x * blockDim.x) {
        float v = xb[i];
        s1 += v; s2 += v * v;
    }
    __shared__ float sm1[256], sm2[256];
    int t = threadIdx.x;
    sm1[t] = s1; sm2[t] = s2;
    __syncthreads();
    for (int o = 128; o > 0; o >>= 1) {
        if (t < o) { sm1[t] += sm1[t + o]; sm2[t] += sm2[t + o]; }
        __syncthreads();
    }
    if (t == 0) {
        g_spart[(b * 64 + blockIdx.x) * 2 + 0] = sm1[0];
        g_spart[(b * 64 + blockIdx.x) * 2 + 1] = sm2[0];
    }
}

__global__ void k_gn_reduce() {
    int b = blockIdx.x, t = threadIdx.x;
    __shared__ float sm1[64], sm2[64];
    sm1[t] = g_spart[(b * 64 + t) * 2 + 0];
    sm2[t] = g_spart[(b * 64 + t) * 2 + 1];
    __syncthreads();
    for (int o = 32; o > 0; o >>= 1) {
        if (t < o) { sm1[t] += sm1[t + o]; sm2[t] += sm2[t + o]; }
        __syncthreads();
    }
    if (t == 0) {
        g_stats[b * 2 + 0] = sm1[0];
        g_stats[b * 2 + 1] = sm2[0];
    }
}

// ---------------- 1b) apply GN -> bf16 ----------------
__global__ void k_xn(const float* __restrict__ x,
                     const float* __restrict__ gnw, const float* __restrict__ gnb) {
    int idx = blockIdx.x * blockDim.x + threadIdx.x;
    if (idx >= BB * CHW / 4) return;
    int fi = idx * 4;
    int b = fi / CHW;
    int rem = fi - b * CHW;
    int c = rem / HWP;
    float s1 = g_stats[b * 2], s2 = g_stats[b * 2 + 1];
    const float invN = 1.0f / (float)CHW;
    float mu = s1 * invN;
    float rstd = rsqrtf(s2 * invN - mu * mu + 1e-5f);
    float sc = rstd * gnw[c];
    float sh = gnb[c] - mu * sc;
    float4 v = *(const float4*)&x[fi];
    bf16* o = &g_xn[fi];
    *(__nv_bfloat162*)o       = __floats2bfloat162_rn(v.x * sc + sh, v.y * sc + sh);
    *(__nv_bfloat162*)(o + 2) = __floats2bfloat162_rn(v.z * sc + sh, v.w * sc + sh);
}

// ---------------- 2) QKV: A=W bf16 m-major, B=xn bf16 k-major ----------------
__global__ void k_qkv(const float* __restrict__ bq, const float* __restrict__ bk,
                      const float* __restrict__ bv) {
    const int b = blockIdx.z;
    const int n0 = blockIdx.x * 128;
    const int m0g = blockIdx.y * 128;
    const int sel = m0g >> 8;
    const int m0 = m0g & 255;
    const bf16* Wsel = g_wb + sel * CC * CC;
    const float* Bias = (sel == 0) ? bq : (sel == 1) ? bk : bv;
    bf16* Out         = (sel == 0) ? g_q : (sel == 1) ? g_k : g_v;
    const bf16* xnb = g_xn + (size_t)b * CHW;

    __shared__ bf16 sA[2][128 * MS];
    __shared__ bf16 sB[2][32 * KS];
    const int tid = threadIdx.x, warp = tid >> 5, lane = tid & 31;
    float acc[2][8][4] = {};

    auto load = [&](int s, int kc) {
        int k0 = kc * 32;
#pragma unroll
        for (int i = 0; i < 2; i++) {
            int idx = tid + i * 256;
            int r = idx >> 2, seg = idx & 3;
            cp16(sptr(&sA[s][r * MS + seg * 8]), Wsel + (m0 + r) * CC + k0 + seg * 8, true);
        }
#pragma unroll
        for (int i = 0; i < 2; i++) {
            int idx = tid + i * 256;
            int r = idx >> 4, seg = idx & 15;
            cp16(sptr(&sB[s][r * KS + seg * 8]), xnb + (size_t)(k0 + r) * HWP + n0 + seg * 8, true);
        }
    };

    const int NK = 8;
    load(0, 0); cp_commit();
    for (int kc = 0; kc < NK; kc++) {
        if (kc + 1 < NK) load((kc + 1) & 1, kc + 1);
        cp_commit();
        cp_wait<1>();
        __syncthreads();
        tile_mma16<false, true>(sA[kc & 1], sB[kc & 1], acc, warp, lane);
        __syncthreads();
    }

    const int gr = lane >> 2, tg = lane & 3;
    const int m0w = 32 * (warp >> 1), n0w = 64 * (warp & 1);
#pragma unroll
    for (int mt = 0; mt < 2; mt++) {
        int mA = m0 + m0w + mt * 16 + gr;
        float bA = Bias[mA], bB = Bias[mA + 8];
#pragma unroll
        for (int nt = 0; nt < 8; nt++) {
            int n = n0 + n0w + nt * 8 + 2 * tg;
            *(unsigned*)&Out[(size_t)(b * CC + mA) * HWP + n] =
                packbf(acc[mt][nt][0] + bA, acc[mt][nt][1] + bA);
            *(unsigned*)&Out[(size_t)(b * CC + mA + 8) * HWP + n] =
                packbf(acc[mt][nt][2] + bB, acc[mt][nt][3] + bB);
        }
    }
}

// ---------------- 3) 2x2 average pool ----------------
__global__ void k_pool() {
    int idx = blockIdx.x * blockDim.x + threadIdx.x;
    if (idx >= BB * CC * A3) return;
    int t = idx % A3;
    int bc = idx / A3;
    int ty = t / TGD, tx = t % TGD;
    size_t base = (size_t)bc * HWP + (size_t)(2 * ty) * WW + 2 * tx;
    g_qp[idx] = __float2bfloat16(0.25f * (__bfloat162float(g_q[base]) + __bfloat162float(g_q[base + 1]) +
                                          __bfloat162float(g_q[base + WW]) + __bfloat162float(g_q[base + WW + 1])));
    g_kp[idx] = __float2bfloat16(0.25f * (__bfloat162float(g_k[base]) + __bfloat162float(g_k[base + 1]) +
                                          __bfloat162float(g_k[base + WW]) + __bfloat162float(g_k[base + WW + 1])));
    g_vp[idx] = __float2bfloat16(0.25f * (__bfloat162float(g_v[base]) + __bfloat162float(g_v[base + 1]) +
                                          __bfloat162float(g_v[base + WW]) + __bfloat162float(g_v[base + WW + 1])));
}

// ---------------- 4) patch logits: A=q, B=k, both k-major; split-K=16 ----------------
__global__ void k_patt() {
    const int bz = blockIdx.z;
    const int b = bz >> 4, ks = bz & 15;
    const int m0 = blockIdx.y * 128, n0 = blockIdx.x * 128;
    const bf16* qb = g_q + (size_t)b * CHW;
    const bf16* kb = g_k + (size_t)b * CHW;

    __shared__ bf16 sA[2][32 * KS];
    __shared__ bf16 sB[2][32 * KS];
    const int tid = threadIdx.x, warp = tid >> 5, lane = tid & 31;
    float acc[2][8][4] = {};

    auto load = [&](int s, int kc) {
        int k0 = ks * 1024 + kc * 32;
#pragma unroll
        for (int i = 0; i < 4; i++) {
            int idx = tid + i * 256;
            int tile = idx >> 9, rem = idx & 511;
            int r = rem >> 4, seg = rem & 15;
            int base0 = tile ? n0 : m0;
            const bf16* gsrc = tile ? kb : qb;
            bf16* st = tile ? &sB[s][0] : &sA[s][0];
            int gm = base0 + seg * 8;
            unsigned dst = sptr(st + r * KS + seg * 8);
            const bf16* sp = gsrc + (size_t)(k0 + r) * PP + gm;
            if (gm + 8 <= PP) {
                cp8(dst, sp);
                cp8(dst + 8, sp + 4);
            } else if (gm < PP) {
                cp8(dst, sp);
            } else {
                cp16(dst, gsrc, false);
            }
        }
    };

    const int NK = 32;
    load(0, 0); cp_commit();
    for (int kc = 0; kc < NK; kc++) {
        if (kc + 1 < NK) load((kc + 1) & 1, kc + 1);
        cp_commit();
        cp_wait<1>();
        __syncthreads();
        tile_mma16<true, true>(sA[kc & 1], sB[kc & 1], acc, warp, lane);
        __syncthreads();
    }

    const float scale = 1.0f / 128.0f;
    const int gr = lane >> 2, tg = lane & 3;
    const int m0w = 32 * (warp >> 1), n0w = 64 * (warp & 1);
    float* ob = g_attp_part + (size_t)(ks * BB + b) * PP * PP;
#pragma unroll
    for (int mt = 0; mt < 2; mt++) {
#pragma unroll
        for (int nt = 0; nt < 8; nt++) {
            int n = n0 + n0w + nt * 8 + 2 * tg;
            if (n >= PP) continue;
            int mA = m0 + m0w + mt * 16 + gr;
            if (mA < PP)
                *(float2*)&ob[(size_t)mA * PP + n] =
                    make_float2(acc[mt][nt][0] * scale, acc[mt][nt][1] * scale);
            if (mA + 8 < PP)
                *(float2*)&ob[(size_t)(mA + 8) * PP + n] =
                    make_float2(acc[mt][nt][2] * scale, acc[mt][nt][3] * scale);
        }
    }
}

// ---------------- 5) patch softmax -> bf16 padded attp ----------------
__global__ void k_psm() {
    int row = blockIdx.x;
    int b = row / PP, p = row % PP;
    __shared__ float srow[PP];
    __shared__ float red[256];
    int t = threadIdx.x;
    for (int q = t; q < PP; q += 256) {
        float s = 0.f;
#pragma unroll
        for (int ks = 0; ks < 16; ks++)
            s += g_attp_part[(size_t)ks * (BB * PP * PP) + (size_t)row * PP + q];
        srow[q] = s;
    }
    __syncthreads();
    float mx = -1e30f;
    for (int q = t; q < PP; q += 256) mx = fmaxf(mx, srow[q]);
    red[t] = mx;
    __syncthreads();
    for (int o = 128; o > 0; o >>= 1) { if (t < o) red[t] = fmaxf(red[t], red[t + o]); __syncthreads(); }
    mx = red[0];
    __syncthreads();
    float s = 0.f;
    for (int q = t; q < PP; q += 256) { float e = __expf(srow[q] - mx); srow[q] = e; s += e; }
    red[t] = s;
    __syncthreads();
    for (int o = 128; o > 0; o >>= 1) { if (t < o) red[t] += red[t + o]; __syncthreads(); }
    float inv = 1.0f / red[0];
    bf16* ob = g_attp + ((size_t)b * 256 + p) * APR;
    for (int q = t; q < PP; q += 256) ob[q] = __float2bfloat16(srow[q] * inv);
}

// ---------------- 6) h_patch = V @ att^T ----------------
__global__ void k_hpatch() {
    const int b = blockIdx.z;
    const int m0 = blockIdx.y * 128;
    const int n0 = blockIdx.x * 128;
    const bf16* vb = g_v + (size_t)b * CHW;
    const bf16* apb = g_attp + (size_t)b * 256 * APR;

    __shared__ bf16 sA[2][128 * MS];
    __shared__ bf16 sB[2][128 * MS];
    const int tid = threadIdx.x, warp = tid >> 5, lane = tid & 31;
    float acc[2][8][4] = {};

    auto load = [&](int s, int kc) {
        int k0 = kc * 32;
#pragma unroll
        for (int i = 0; i < 4; i++) {
            int idx = tid + i * 256;
            int tile = idx >> 9, rem = idx & 511;
            int r = rem >> 2, seg = rem & 3;
            if (tile == 0) {
                unsigned dst = sptr(&sA[s][r * MS + seg * 8]);
                const bf16* sp = vb + (size_t)(m0 + r) * PP + k0 + seg * 8;
                cp8(dst, sp);
                cp8(dst + 8, sp + 4);
            } else {
                cp16(sptr(&sB[s][r * MS + seg * 8]),
                     apb + (size_t)(n0 + r) * APR + k0 + seg * 8, true);
            }
        }
    };

    const int NK = 7;
    load(0, 0); cp_commit();
    for (int kc = 0; kc < NK; kc++) {
        if (kc + 1 < NK) load((kc + 1) & 1, kc + 1);
        cp_commit();
        cp_wait<1>();
        __syncthreads();
        tile_mma16<false, false>(sA[kc & 1], sB[kc & 1], acc, warp, lane);
        __syncthreads();
    }

    const int gr = lane >> 2, tg = lane & 3;
    const int m0w = 32 * (warp >> 1), n0w = 64 * (warp & 1);
    bf16* ob = g_hpatch + (size_t)b * CHW;
#pragma unroll
    for (int mt = 0; mt < 2; mt++) {
        int mA = m0 + m0w + mt * 16 + gr;
#pragma unroll
        for (int nt = 0; nt < 8; nt++) {
            int n = n0 + n0w + nt * 8 + 2 * tg;
            if (n >= PP) continue;
            *(unsigned*)&ob[(size_t)mA * PP + n] = packbf(acc[mt][nt][0], acc[mt][nt][1]);
            *(unsigned*)&ob[(size_t)(mA + 8) * PP + n] = packbf(acc[mt][nt][2], acc[mt][nt][3]);
        }
    }
}

// ---------------- 7) flash global attention (restructured: full-chunk K, 5 barriers/chunk) ----------------
// 512 threads / 16 warps. Q tile 64 pos x 256 ch resident; kv chunks of 128.
// S phase: warp w -> m-slab 16*(w>>2), n-slab 32*(w&3).  PV: d-slab 64*(w&3).
__global__ void k_fglob() {
    extern __shared__ bf16 fsm[];
    bf16* sQ = fsm;                       // [256][FQS]
    bf16* sK = sQ + 256 * FQS;            // [256][FKS] full chunk: 256 ch x 128 kv
    bf16* sP = sK + 256 * FKS;            // [64][FPS]
    bf16* sV = sP + 64 * FPS;             // [256][FVS]
    float* sMax = (float*)(sV + 256 * FVS);   // [4][64]
    float* sSum = sMax + 256;                 // [4][64]

    const int b = blockIdx.y;
    const int q0 = blockIdx.x * 64;
    const bf16* qp = g_qp + (size_t)b * CC * A3;
    const bf16* kp = g_kp + (size_t)b * CC * A3;
    const bf16* vp = g_vp + (size_t)b * CC * A3;

    const int tid = threadIdx.x, warp = tid >> 5, lane = tid & 31;
    const int mw = 16 * (warp >> 2);
    const int nw = 32 * (warp & 3);
    const int dw = 64 * (warp & 3);
    const int j = lane >> 3, i = lane & 7;
    const int gr = lane >> 2, tg = lane & 3;

    // full 256x128 K chunk load: 4096 cp16, 8 per thread
    auto loadK = [&](int kv0) {
#pragma unroll
        for (int it = 0; it < 8; it++) {
            int idx = tid + it * 512;
            int c = idx >> 4, seg = idx & 15;
            int q = kv0 + seg * 8;
            bool v = q < A3;
            cp16(sptr(&sK[c * FKS + seg * 8]), kp + (size_t)c * A3 + (v ? q : 0), v);
        }
    };
    auto loadV = [&](int kv0) {
#pragma unroll
        for (int it = 0; it < 8; it++) {
            int idx = tid + it * 512;
            int d = idx >> 4, seg = idx & 15;
            int q = kv0 + seg * 8;
            bool v = q < A3;
            cp16(sptr(&sV[d * FVS + seg * 8]), vp + (size_t)d * A3 + (v ? q : 0), v);
        }
    };

    // Q tile (2048 cp16) + K chunk 0, single group
#pragma unroll
    for (int it = 0; it < 4; it++) {
        int idx = tid + it * 512;
        int c = idx >> 3, seg = idx & 7;
        cp16(sptr(&sQ[c * FQS + seg * 8]), qp + (size_t)c * A3 + q0 + seg * 8, true);
    }
    loadK(0);
    cp_commit();

    float m_r[2] = {-1e30f, -1e30f}, l_r[2] = {0.f, 0.f};
    float acc_o[8][4] = {};

    const int NCH = 25;                  // ceil(3136/128); last chunk half-valid
    for (int ch = 0; ch < NCH; ch++) {
        const int kv0 = ch * 128;

        cp_wait<0>();                    // K(ch) (+Q on first iter) arrived
        __syncthreads();

        // V(ch) buffer is free (post-PV sync last iter) -> hide its load under S phase
        loadV(kv0);
        cp_commit();

        // ---- S = Q K^T : 8 cc-chunks of 32 channels, NO barriers ----
        float acc_s[4][4] = {};
#pragma unroll
        for (int cc = 0; cc < 8; cc++) {
            const int cq = cc * 32;
#pragma unroll
            for (int kt = 0; kt < 2; kt++) {
                unsigned a[4];
                ldsm4t(a, sptr(&sQ[(cq + kt * 16 + (j >> 1) * 8 + i) * FQS + mw + (j & 1) * 8]));
#pragma unroll
                for (int ng = 0; ng < 2; ng++) {
                    unsigned bb[4];
                    ldsm4t(bb, sptr(&sK[(cq + kt * 16 + (j & 1) * 8 + i) * FKS + nw + ng * 16 + (j >> 1) * 8]));
                    mma16(acc_s[ng * 2],     a, bb[0], bb[1]);
                    mma16(acc_s[ng * 2 + 1], a, bb[2], bb[3]);
                }
            }
        }

        // ---- online softmax ----
        float mx[2] = {-1e30f, -1e30f};
#pragma unroll
        for (int nt = 0; nt < 4; nt++) {
            int col = kv0 + nw + nt * 8 + 2 * tg;
#pragma unroll
            for (int e = 0; e < 4; e++) {
                float s = acc_s[nt][e] * 0.0625f;        // C^-0.5
                s = ((col + (e & 1)) < A3) ? s : -1e30f;
                acc_s[nt][e] = s;
                mx[e >> 1] = fmaxf(mx[e >> 1], s);
            }
        }
#pragma unroll
        for (int o = 1; o < 4; o <<= 1) {
            mx[0] = fmaxf(mx[0], __shfl_xor_sync(~0u, mx[0], o));
            mx[1] = fmaxf(mx[1], __shfl_xor_sync(~0u, mx[1], o));
        }
        if (tg == 0) {
            sMax[(warp & 3) * 64 + mw + gr]     = mx[0];
            sMax[(warp & 3) * 64 + mw + 8 + gr] = mx[1];
        }
        __syncthreads();                 // also: all warps finished reading sK
        float mnew[2], alpha[2];
#pragma unroll
        for (int h = 0; h < 2; h++) {
            int r = mw + h * 8 + gr;
            float cm = fmaxf(fmaxf(sMax[r], sMax[64 + r]), fmaxf(sMax[128 + r], sMax[192 + r]));
            mnew[h] = fmaxf(m_r[h], cm);
            alpha[h] = __expf(m_r[h] - mnew[h]);
            m_r[h] = mnew[h];
        }
        float sum[2] = {0.f, 0.f};
#pragma unroll
        for (int nt = 0; nt < 4; nt++) {
            int col = nw + nt * 8 + 2 * tg;
            float p0 = __expf(acc_s[nt][0] - mnew[0]);
            float p1 = __expf(acc_s[nt][1] - mnew[0]);
            float p2 = __expf(acc_s[nt][2] - mnew[1]);
            float p3 = __expf(acc_s[nt][3] - mnew[1]);
            sum[0] += p0 + p1;
            sum[1] += p2 + p3;
            *(unsigned*)&sP[(mw + gr) * FPS + col]     = packbf(p0, p1);
            *(unsigned*)&sP[(mw + 8 + gr) * FPS + col] = packbf(p2, p3);
        }
#pragma unroll
        for (int o = 1; o < 4; o <<= 1) {
            sum[0] += __shfl_xor_sync(~0u, sum[0], o);
            sum[1] += __shfl_xor_sync(~0u, sum[1], o);
        }
        if (tg == 0) {
            sSum[(warp & 3) * 64 + mw + gr]     = sum[0];
            sSum[(warp & 3) * 64 + mw + 8 + gr] = sum[1];
        }
        // rescale O accumulators
#pragma unroll
        for (int nt = 0; nt < 8; nt++) {
            acc_o[nt][0] *= alpha[0]; acc_o[nt][1] *= alpha[0];
            acc_o[nt][2] *= alpha[1]; acc_o[nt][3] *= alpha[1];
        }
        __syncthreads();
#pragma unroll
        for (int h = 0; h < 2; h++) {
            int r = mw + h * 8 + gr;
            l_r[h] = l_r[h] * alpha[h] + sSum[r] + sSum[64 + r] + sSum[128 + r] + sSum[192 + r];
        }

        // sK free (all warps past S) -> stream next K under PV compute
        if (ch + 1 < NCH) loadK(kv0 + 128);
        cp_commit();                     // group even if empty (keeps FIFO depth consistent)

        cp_wait<1>();                    // V(ch) arrived; K(ch+1) still in flight
        __syncthreads();

        // ---- O += P V : k=q (8 kt of 16), d-slab dw (4 groups of 16) ----
#pragma unroll
        for (int kt = 0; kt < 8; kt++) {
            unsigned a[4];
            ldsm4(a, sptr(&sP[(mw + (j & 1) * 8 + i) * FPS + kt * 16 + (j >> 1) * 8]));
#pragma unroll
            for (int ng = 0; ng < 4; ng++) {
                unsigned bb[4];
                ldsm4(bb, sptr(&sV[(dw + ng * 16 + (j >> 1) * 8 + i) * FVS + kt * 16 + (j & 1) * 8]));
                mma16(acc_o[ng * 2],     a, bb[0], bb[1]);
                mma16(acc_o[ng * 2 + 1], a, bb[2], bb[3]);
            }
        }
        __syncthreads();                 // sV/sP free for next chunk
    }

    // ---- epilogue: O /= l, write hglob[c][pos] ----
    bf16* ob = g_hglob + (size_t)b * CC * A3;
    float invl[2] = {1.f / l_r[0], 1.f / l_r[1]};
    int p0 = q0 + mw + gr, p1 = p0 + 8;
#pragma unroll
    for (int nt = 0; nt < 8; nt++) {
        int d = dw + (nt >> 1) * 16 + (nt & 1) * 8 + 2 * tg;
        ob[(size_t)d * A3 + p0]       = __float2bfloat16(acc_o[nt][0] * invl[0]);
        ob[(size_t)(d + 1) * A3 + p0] = __float2bfloat16(acc_o[nt][1] * invl[0]);
        ob[(size_t)d * A3 + p1]       = __float2bfloat16(acc_o[nt][2] * invl[1]);
        ob[(size_t)(d + 1) * A3 + p1] = __float2bfloat16(acc_o[nt][3] * invl[1]);
    }
}

// ---------------- 10) combine -> bf16 h ----------------
__global__ void k_comb() {
    int idx = blockIdx.x * blockDim.x + threadIdx.x;
    if (idx >= BB * CHW) return;
    int hw = idx % HWP;
    int bc = idx / HWP;
    int i = hw / WW, j = hw % WW;
    float sy = 0.5f * i - 0.25f;
    int y0 = (int)floorf(sy);
    float fy = sy - (float)y0;
    int y0c = max(y0, 0), y1c = min(y0 + 1, TGD - 1);
    float sx = 0.5f * j - 0.25f;
    int x0 = (int)floorf(sx);
    float fx = sx - (float)x0;
    int x0c = max(x0, 0), x1c = min(x0 + 1, TGD - 1);
    const bf16* hg = g_hglob + (size_t)bc * A3;
    float v00 = __bfloat162float(hg[y0c * TGD + x0c]), v01 = __bfloat162float(hg[y0c * TGD + x1c]);
    float v10 = __bfloat162float(hg[y1c * TGD + x0c]), v11 = __bfloat162float(hg[y1c * TGD + x1c]);
    float bil = (1.f - fy) * ((1.f - fx) * v00 + fx * v01) +
                fy * ((1.f - fx) * v10 + fx * v11);
    g_h[idx] = __float2bfloat16(0.75f * __bfloat162float(g_hpatch[idx]) + 0.25f * bil);
}

// ---------------- 11) proj + residual ----------------
__global__ void k_proj(const float* __restrict__ x, float* __restrict__ out) {
    const int b = blockIdx.z;
    const int m0 = blockIdx.y * 128;
    const int n0 = blockIdx.x * 128;
    const bf16* hb = g_h + (size_t)b * CHW;
    const bf16* Wp = g_wb + 3 * CC * CC;

    __shared__ bf16 sA[2][128 * MS];
    __shared__ bf16 sB[2][32 * KS];
    const int tid = threadIdx.x, warp = tid >> 5, lane = tid & 31;
    float acc[2][8][4] = {};

    auto load = [&](int s, int kc) {
        int k0 = kc * 32;
#pragma unroll
        for (int i = 0; i < 2; i++) {
            int idx = tid + i * 256;
            int r = idx >> 2, seg = idx & 3;
            cp16(sptr(&sA[s][r * MS + seg * 8]), Wp + (m0 + r) * CC + k0 + seg * 8, true);
        }
#pragma unroll
        for (int i = 0; i < 2; i++) {
            int idx = tid + i * 256;
            int r = idx >> 4, seg = idx & 15;
            cp16(sptr(&sB[s][r * KS + seg * 8]), hb + (size_t)(k0 + r) * HWP + n0 + seg * 8, true);
        }
    };

    const int NK = 8;
    load(0, 0); cp_commit();
    for (int kc = 0; kc < NK; kc++) {
        if (kc + 1 < NK) load((kc + 1) & 1, kc + 1);
        cp_commit();
        cp_wait<1>();
        __syncthreads();
        tile_mma16<false, true>(sA[kc & 1], sB[kc & 1], acc, warp, lane);
        __syncthreads();
    }

    const int gr = lane >> 2, tg = lane & 3;
    const int m0w = 32 * (warp >> 1), n0w = 64 * (warp & 1);
#pragma unroll
    for (int mt = 0; mt < 2; mt++) {
        int mA = m0 + m0w + mt * 16 + gr;
#pragma unroll
        for (int nt = 0; nt < 8; nt++) {
            int n = n0 + n0w + nt * 8 + 2 * tg;
            size_t o0 = (size_t)b * CHW + (size_t)mA * HWP + n;
            size_t o1 = (size_t)b * CHW + (size_t)(mA + 8) * HWP + n;
            float2 x0 = *(const float2*)&x[o0];
            float2 x1 = *(const float2*)&x[o1];
            *(float2*)&out[o0] = make_float2(x0.x + acc[mt][nt][0], x0.y + acc[mt][nt][1]);
            *(float2*)&out[o1] = make_float2(x1.x + acc[mt][nt][2], x1.y + acc[mt][nt][3]);
        }
    }
}

// ---------------- launch ----------------
extern "C" void kernel_launch(void* const* d_in, const int* in_sizes, int n_in,
                              void* d_out, int out_size) {
    const float* x   = (const float*)d_in[0];
    const float* gnw = (const float*)d_in[1];
    const float* gnb = (const float*)d_in[2];
    const float* wq  = (const float*)d_in[3];
    const float* bq  = (const float*)d_in[4];
    const float* wk  = (const float*)d_in[5];
    const float* bk  = (const float*)d_in[6];
    const float* wv  = (const float*)d_in[7];
    const float* bv  = (const float*)d_in[8];
    const float* wp  = (const float*)d_in[9];
    float* out = (float*)d_out;

    static bool attr_set = false;
    if (!attr_set) {
        cudaFuncSetAttribute(k_fglob, cudaFuncAttributeMaxDynamicSharedMemorySize, SMEM_FG);
        attr_set = true;
    }

    k_wprep<<<(4 * CC * CC + 255) / 256, 256>>>(wq, wk, wv, wp);
    k_gn_stats<<<dim3(64, 8), 256>>>(x);
    k_gn_reduce<<<8, 64>>>();
    k_xn<<<(BB * CHW / 4 + 255) / 256, 256>>>(x, gnw, gnb);
    k_qkv<<<dim3(98, 6, 8), 256>>>(bq, bk, bv);
    k_pool<<<(BB * CC * A3 + 255) / 256, 256>>>();
    k_patt<<<dim3(2, 2, 128), 256>>>();
    k_psm<<<BB * PP, 256>>>();
    k_hpatch<<<dim3(2, 128, 8), 256>>>();
    k_fglob<<<dim3(49, 8), 512, SMEM_FG>>>();
    k_comb<<<(BB * CHW + 255) / 256, 256>>>();
    k_proj<<<dim3(98, 2, 8), 256>>>(x, out);
}